// round 4
// baseline (speedup 1.0000x reference)
#include <cuda_runtime.h>
#include <math.h>

// Problem constants
#define B_  8192
#define T_  128
#define D_  7
#define I_  128
#define C_  10
#define L_  128
#define TD_ 896          // T_*D_
#define LPROW 24         // duplicated leafP row: 10 classes x {v,v} = 20, pad to 24

typedef unsigned long long u64x;

__device__ __forceinline__ u64x pk2(float lo, float hi) {
    u64x r; asm("mov.b64 %0, {%1, %2};" : "=l"(r) : "f"(lo), "f"(hi)); return r;
}
__device__ __forceinline__ void upk2(float& lo, float& hi, u64x v) {
    asm("mov.b64 {%0, %1}, %2;" : "=f"(lo), "=f"(hi) : "l"(v));
}
__device__ __forceinline__ u64x mul2_(u64x a, u64x b) {
    u64x d; asm("mul.rn.f32x2 %0, %1, %2;" : "=l"(d) : "l"(a), "l"(b)); return d;
}
__device__ __forceinline__ u64x fma2_(u64x a, u64x b, u64x c) {
    u64x d; asm("fma.rn.f32x2 %0, %1, %2, %3;" : "=l"(d) : "l"(a), "l"(b), "l"(c)); return d;
}
__device__ __forceinline__ u64x d2u(double v) { return (u64x)__double_as_longlong(v); }

// ---------------- scratch (__device__ globals; no allocation) ----------------
__device__ float g_LP[T_ * L_ * LPROW];            // softmaxed leaf probs, duplicated pairs
__device__ float g_attn[T_ * B_];                  // attention, TRANSPOSED [t][b]
__device__ float g_s[(size_t)TD_ * B_];            // softsign(z), TRANSPOSED [t*7+d][b]
__device__ float g_part[4 * B_ * C_];              // kmix partials (tree-split 4)

// ---------------- kernel 1: leaf softmax -> duplicated pairs ----------------
__global__ __launch_bounds__(256)
void prep_leaf_kernel(const float* __restrict__ leaf, float* __restrict__ lp) {
    int idx = blockIdx.x * blockDim.x + threadIdx.x;   // t*128 + l
    if (idx >= T_ * L_) return;
    const float* in = leaf + (size_t)idx * C_;
    float v[C_];
    float m = -1e30f;
    #pragma unroll
    for (int c = 0; c < C_; c++) { v[c] = in[c]; m = fmaxf(m, v[c]); }
    float sum = 0.f;
    #pragma unroll
    for (int c = 0; c < C_; c++) { v[c] = expf(v[c] - m); sum += v[c]; }
    float inv = 1.0f / sum;
    float* o = lp + (size_t)idx * LPROW;
    #pragma unroll
    for (int c = 0; c < C_; c++) { float p = v[c] * inv; o[2*c] = p; o[2*c+1] = p; }
    o[20] = 0.f; o[21] = 0.f; o[22] = 0.f; o[23] = 0.f;
}

// ---------------- kernel 2: MLP attention (warp per row b), transposed out ----
__global__ __launch_bounds__(256)
void attn_kernel(const float* __restrict__ x,  const float* __restrict__ W1,
                 const float* __restrict__ b1, const float* __restrict__ W2,
                 const float* __restrict__ b2, float* __restrict__ attn_out) {
    __shared__ float sx[8][128];
    __shared__ float sh[8][64];
    int w = threadIdx.x >> 5, lane = threadIdx.x & 31;
    int b = blockIdx.x * 8 + w;

    #pragma unroll
    for (int k = 0; k < 4; k++) sx[w][lane + 32 * k] = x[(size_t)b * I_ + lane + 32 * k];
    __syncwarp();

    float h0 = b1[lane], h1 = b1[lane + 32];
    #pragma unroll 4
    for (int i = 0; i < I_; i++) {
        float xi = sx[w][i];
        h0 = fmaf(xi, W1[i * 64 + lane],      h0);
        h1 = fmaf(xi, W1[i * 64 + lane + 32], h1);
    }
    sh[w][lane]      = fmaxf(h0, 0.f);
    sh[w][lane + 32] = fmaxf(h1, 0.f);
    __syncwarp();

    float lg[4];
    #pragma unroll
    for (int k = 0; k < 4; k++) lg[k] = b2[lane + 32 * k];
    #pragma unroll 4
    for (int j = 0; j < 64; j++) {
        float hj = sh[w][j];
        #pragma unroll
        for (int k = 0; k < 4; k++)
            lg[k] = fmaf(hj, W2[j * T_ + lane + 32 * k], lg[k]);
    }
    float m = fmaxf(fmaxf(lg[0], lg[1]), fmaxf(lg[2], lg[3]));
    #pragma unroll
    for (int o = 16; o; o >>= 1) m = fmaxf(m, __shfl_xor_sync(0xffffffffu, m, o));
    float sum = 0.f;
    #pragma unroll
    for (int k = 0; k < 4; k++) { lg[k] = expf(lg[k] - m); sum += lg[k]; }
    #pragma unroll
    for (int o = 16; o; o >>= 1) sum += __shfl_xor_sync(0xffffffffu, sum, o);
    float inv = 1.0f / sum;
    #pragma unroll
    for (int k = 0; k < 4; k++)
        attn_out[(size_t)(lane + 32 * k) * B_ + b] = lg[k] * inv;   // transposed
}

// ---------------- kernel 3: z GEMM (packed f32x2) + softsign, transposed out --
// tile: M=32 b-rows x N=128, K=128 resident. thread: 4 m (packed dup A) x 4 n.
// smem: As_dup [k=128][64] pad 68  (m duplicated pairs {a,a})
//       Bs     [k=128][128] pad 132
#define KZ_SMEM_FLOATS (128 * 68 + 128 * 132)
__global__ __launch_bounds__(256)
void kz_kernel(const float* __restrict__ x, const float* __restrict__ fm,
               const float* __restrict__ thr, float* __restrict__ s_out) {
    extern __shared__ float smz[];
    float* Asd = smz;                 // [128][68]
    float* Bs  = smz + 128 * 68;      // [128][132]
    int tid = threadIdx.x;
    int b0 = blockIdx.x * 32;
    int n0 = blockIdx.y * 128;

    // fill As_dup: thread (m, k4), lanes over k4 -> coalesced row reads
    for (int idx = tid; idx < 32 * 32; idx += 256) {
        int m = idx >> 5, k4 = idx & 31;
        float4 xv = *(const float4*)&x[(size_t)(b0 + m) * I_ + 4 * k4];
        *(u64x*)&Asd[(4 * k4 + 0) * 68 + 2 * m] = pk2(xv.x, xv.x);
        *(u64x*)&Asd[(4 * k4 + 1) * 68 + 2 * m] = pk2(xv.y, xv.y);
        *(u64x*)&Asd[(4 * k4 + 2) * 68 + 2 * m] = pk2(xv.z, xv.z);
        *(u64x*)&Asd[(4 * k4 + 3) * 68 + 2 * m] = pk2(xv.w, xv.w);
    }
    // fill Bs
    for (int idx = tid; idx < 128 * 32; idx += 256) {
        int n = idx >> 5, k4 = idx & 31;
        float4 fv = *(const float4*)&fm[(size_t)(n0 + n) * I_ + 4 * k4];
        Bs[(4 * k4 + 0) * 132 + n] = fv.x;
        Bs[(4 * k4 + 1) * 132 + n] = fv.y;
        Bs[(4 * k4 + 2) * 132 + n] = fv.z;
        Bs[(4 * k4 + 3) * 132 + n] = fv.w;
    }
    __syncthreads();

    int tn = tid & 31, tb = tid >> 5;       // tb uniform in warp -> A broadcast
    u64x acc[4][2];
    #pragma unroll
    for (int i = 0; i < 4; i++) { acc[i][0] = 0; acc[i][1] = 0; }

    const float* aP = Asd + 8 * tb;
    const float* bP = Bs + 4 * tn;
    #pragma unroll 8
    for (int k = 0; k < 128; k++) {
        double2 ad0 = *(const double2*)(aP + k * 68);      // {a0,a0},{a1,a1}
        double2 ad1 = *(const double2*)(aP + k * 68 + 4);  // {a2,a2},{a3,a3}
        double2 bd  = *(const double2*)(bP + k * 132);     // {b0,b1},{b2,b3}
        u64x b01 = d2u(bd.x), b23 = d2u(bd.y);
        u64x a0 = d2u(ad0.x), a1 = d2u(ad0.y), a2 = d2u(ad1.x), a3 = d2u(ad1.y);
        acc[0][0] = fma2_(a0, b01, acc[0][0]); acc[0][1] = fma2_(a0, b23, acc[0][1]);
        acc[1][0] = fma2_(a1, b01, acc[1][0]); acc[1][1] = fma2_(a1, b23, acc[1][1]);
        acc[2][0] = fma2_(a2, b01, acc[2][0]); acc[2][1] = fma2_(a2, b23, acc[2][1]);
        acc[3][0] = fma2_(a3, b01, acc[3][0]); acc[3][1] = fma2_(a3, b23, acc[3][1]);
    }

    float av[4][4];
    #pragma unroll
    for (int i = 0; i < 4; i++) {
        upk2(av[i][0], av[i][1], acc[i][0]);
        upk2(av[i][2], av[i][3], acc[i][1]);
    }
    int bcol = b0 + tb * 4;
    #pragma unroll
    for (int jn = 0; jn < 4; jn++) {
        int n = n0 + tn * 4 + jn;
        float th = thr[n];
        float4 o;
        float z0 = av[0][jn] - th, z1 = av[1][jn] - th;
        float z2 = av[2][jn] - th, z3 = av[3][jn] - th;
        o.x = fmaf(0.5f, __fdividef(z0, 1.0f + fabsf(z0)), 0.5f);
        o.y = fmaf(0.5f, __fdividef(z1, 1.0f + fabsf(z1)), 0.5f);
        o.z = fmaf(0.5f, __fdividef(z2, 1.0f + fabsf(z2)), 0.5f);
        o.w = fmaf(0.5f, __fdividef(z3, 1.0f + fabsf(z3)), 0.5f);
        *(float4*)&s_out[(size_t)n * B_ + bcol] = o;   // transposed [n][b]
    }
}

// ---------------- kernel 4: leaf products + mix (packed), tree-split 4 -------
// grid (128 b-blocks, 4 tree-splits). block 256 = 8 warps.
// warp w handles 4 trees: ts*32 + w*4 + tt. lanes: b_lo = bb*64+lane, b_hi = +32.
#define KMIX_SMEM_FLOATS (8 * L_ * LPROW)     // 8 warp slabs x 128 leaves x 24
__global__ __launch_bounds__(256)
void kmix_kernel(const float* __restrict__ s_in, const float* __restrict__ attn,
                 const float* __restrict__ lp, float* __restrict__ part) {
    extern __shared__ float smm[];
    int w = threadIdx.x >> 5, lane = threadIdx.x & 31;
    int bbase = blockIdx.x * 64;
    int ts = blockIdx.y;

    const u64x ONE2 = 0x3f8000003f800000ULL;
    const u64x NEG2 = 0xbf800000bf800000ULL;

    u64x acc[C_];
    #pragma unroll
    for (int c = 0; c < C_; c++) acc[c] = 0;

    float* myLP = smm + w * (L_ * LPROW);

    for (int tt = 0; tt < 4; tt++) {
        int t = ts * 32 + w * 4 + tt;
        __syncwarp();
        // stage duplicated LP[t] slab: 3072 floats = 768 float4
        const float4* src = (const float4*)(lp + (size_t)t * (L_ * LPROW));
        float4* dst = (float4*)myLP;
        #pragma unroll
        for (int k = 0; k < 24; k++) dst[lane + 32 * k] = src[lane + 32 * k];
        __syncwarp();

        // packed s, mv
        u64x sv[D_], mv[D_];
        const float* sp = s_in + (size_t)(t * D_) * B_ + bbase + lane;
        #pragma unroll
        for (int d = 0; d < D_; d++) {
            sv[d] = pk2(sp[(size_t)d * B_], sp[(size_t)d * B_ + 32]);
            mv[d] = fma2_(sv[d], NEG2, ONE2);          // 1 - s
        }
        const float* ap = attn + (size_t)t * B_ + bbase + lane;
        u64x a2 = pk2(ap[0], ap[32]);

        // pLow bits 0..2
        u64x pl[8];
        pl[0] = sv[0]; pl[1] = mv[0];
        pl[2] = mul2_(pl[0], mv[1]); pl[3] = mul2_(pl[1], mv[1]);
        pl[0] = mul2_(pl[0], sv[1]); pl[1] = mul2_(pl[1], sv[1]);
        pl[4] = mul2_(pl[0], mv[2]); pl[5] = mul2_(pl[1], mv[2]);
        pl[6] = mul2_(pl[2], mv[2]); pl[7] = mul2_(pl[3], mv[2]);
        pl[0] = mul2_(pl[0], sv[2]); pl[1] = mul2_(pl[1], sv[2]);
        pl[2] = mul2_(pl[2], sv[2]); pl[3] = mul2_(pl[3], sv[2]);
        // pHigh bits 3..6, attention folded at level 0
        u64x ph[16];
        ph[0] = mul2_(a2, sv[3]); ph[1] = mul2_(a2, mv[3]);
        ph[2] = mul2_(ph[0], mv[4]); ph[3] = mul2_(ph[1], mv[4]);
        ph[0] = mul2_(ph[0], sv[4]); ph[1] = mul2_(ph[1], sv[4]);
        ph[4] = mul2_(ph[0], mv[5]); ph[5] = mul2_(ph[1], mv[5]);
        ph[6] = mul2_(ph[2], mv[5]); ph[7] = mul2_(ph[3], mv[5]);
        ph[0] = mul2_(ph[0], sv[5]); ph[1] = mul2_(ph[1], sv[5]);
        ph[2] = mul2_(ph[2], sv[5]); ph[3] = mul2_(ph[3], sv[5]);
        #pragma unroll
        for (int j = 0; j < 8; j++) ph[8 + j] = mul2_(ph[j], mv[6]);
        #pragma unroll
        for (int j = 0; j < 8; j++) ph[j] = mul2_(ph[j], sv[6]);

        // mix: per leaf 5x broadcast LDS.128 + 1 MUL2 + 10 FFMA2
        #pragma unroll
        for (int m = 0; m < 16; m++) {
            u64x phm = ph[m];
            #pragma unroll
            for (int j = 0; j < 8; j++) {
                const float* Lr = myLP + (m * 8 + j) * LPROW;
                double2 L0 = *(const double2*)(Lr);
                double2 L1 = *(const double2*)(Lr + 4);
                double2 L2 = *(const double2*)(Lr + 8);
                double2 L3 = *(const double2*)(Lr + 12);
                double2 L4 = *(const double2*)(Lr + 16);
                u64x q = mul2_(pl[j], phm);
                acc[0] = fma2_(q, d2u(L0.x), acc[0]); acc[1] = fma2_(q, d2u(L0.y), acc[1]);
                acc[2] = fma2_(q, d2u(L1.x), acc[2]); acc[3] = fma2_(q, d2u(L1.y), acc[3]);
                acc[4] = fma2_(q, d2u(L2.x), acc[4]); acc[5] = fma2_(q, d2u(L2.y), acc[5]);
                acc[6] = fma2_(q, d2u(L3.x), acc[6]); acc[7] = fma2_(q, d2u(L3.y), acc[7]);
                acc[8] = fma2_(q, d2u(L4.x), acc[8]); acc[9] = fma2_(q, d2u(L4.y), acc[9]);
            }
        }
    }

    // in-block reduction over 8 warps (reuse slab smem)
    __syncthreads();
    u64x* sr = (u64x*)smm;                     // [8][32][10] u64
    #pragma unroll
    for (int c = 0; c < C_; c++) sr[(w * 32 + lane) * C_ + c] = acc[c];
    __syncthreads();
    if (threadIdx.x < 64) {
        int bb = threadIdx.x;                  // local b 0..63
        int sel = bb >> 5, ln = bb & 31;
        const float* srf = (const float*)sr;
        float v[C_];
        #pragma unroll
        for (int c = 0; c < C_; c++) {
            float s = 0.f;
            #pragma unroll
            for (int ww = 0; ww < 8; ww++)
                s += srf[((ww * 32 + ln) * C_ + c) * 2 + sel];
            v[c] = s;
        }
        float* o = part + ((size_t)ts * B_ + bbase + bb) * C_;
        #pragma unroll
        for (int c = 0; c < C_; c++) o[c] = v[c];
    }
}

// ---------------- kernel 5: sum the 4 tree-split partials ----------------
__global__ __launch_bounds__(256)
void reduce_kernel(const float* __restrict__ part, float* __restrict__ out) {
    int i = blockIdx.x * blockDim.x + threadIdx.x;
    if (i >= B_ * C_) return;
    out[i] = part[i] + part[B_ * C_ + i] + part[2 * B_ * C_ + i] + part[3 * B_ * C_ + i];
}

// ---------------- launcher ----------------
extern "C" void kernel_launch(void* const* d_in, const int* in_sizes, int n_in,
                              void* d_out, int out_size) {
    const float* x    = (const float*)d_in[0];
    const float* fm   = (const float*)d_in[1];
    const float* thr  = (const float*)d_in[2];
    const float* leaf = (const float*)d_in[3];
    const float* W1   = (const float*)d_in[4];
    const float* b1   = (const float*)d_in[5];
    const float* W2   = (const float*)d_in[6];
    const float* b2   = (const float*)d_in[7];
    float* out = (float*)d_out;

    float *gLP, *gAt, *gS, *gP;
    cudaGetSymbolAddress((void**)&gLP, g_LP);
    cudaGetSymbolAddress((void**)&gAt, g_attn);
    cudaGetSymbolAddress((void**)&gS,  g_s);
    cudaGetSymbolAddress((void**)&gP,  g_part);

    cudaFuncSetAttribute(kz_kernel,   cudaFuncAttributeMaxDynamicSharedMemorySize,
                         KZ_SMEM_FLOATS * 4);
    cudaFuncSetAttribute(kmix_kernel, cudaFuncAttributeMaxDynamicSharedMemorySize,
                         KMIX_SMEM_FLOATS * 4);
    (void)in_sizes; (void)n_in; (void)out_size;

    prep_leaf_kernel<<<(T_ * L_ + 255) / 256, 256>>>(leaf, gLP);
    attn_kernel<<<B_ / 8, 256>>>(x, W1, b1, W2, b2, gAt);
    kz_kernel<<<dim3(B_ / 32, TD_ / 128), 256, KZ_SMEM_FLOATS * 4>>>(x, fm, thr, gS);
    kmix_kernel<<<dim3(B_ / 64, 4), 256, KMIX_SMEM_FLOATS * 4>>>(gS, gAt, gLP, gP);
    reduce_kernel<<<(B_ * C_ + 255) / 256, 256>>>(gP, out);
}

// round 5
// speedup vs baseline: 1.1205x; 1.1205x over previous
#include <cuda_runtime.h>
#include <math.h>

// Problem constants
#define B_  8192
#define T_  128
#define D_  7
#define I_  128
#define C_  10
#define L_  128
#define TD_ 896          // T_*D_
#define LPROW 24         // duplicated leafP row: 10 classes x {v,v} = 20, pad to 24
#define NSPLIT 8         // kmix tree splits

typedef unsigned long long u64x;

__device__ __forceinline__ u64x pk2(float lo, float hi) {
    u64x r; asm("mov.b64 %0, {%1, %2};" : "=l"(r) : "f"(lo), "f"(hi)); return r;
}
__device__ __forceinline__ void upk2(float& lo, float& hi, u64x v) {
    asm("mov.b64 {%0, %1}, %2;" : "=f"(lo), "=f"(hi) : "l"(v));
}
__device__ __forceinline__ u64x mul2_(u64x a, u64x b) {
    u64x d; asm("mul.rn.f32x2 %0, %1, %2;" : "=l"(d) : "l"(a), "l"(b)); return d;
}
__device__ __forceinline__ u64x fma2_(u64x a, u64x b, u64x c) {
    u64x d; asm("fma.rn.f32x2 %0, %1, %2, %3;" : "=l"(d) : "l"(a), "l"(b), "l"(c)); return d;
}
__device__ __forceinline__ u64x d2u(double v) { return (u64x)__double_as_longlong(v); }

// ---------------- scratch (__device__ globals; no allocation) ----------------
__device__ float g_LP[T_ * L_ * LPROW];            // softmaxed leaf probs, duplicated pairs
__device__ float g_attn[T_ * B_];                  // attention, TRANSPOSED [t][b]
__device__ float g_s[(size_t)TD_ * B_];            // softsign(z), TRANSPOSED [t*7+d][b]
__device__ float g_part[NSPLIT * B_ * C_];         // kmix partials

// ---------------- kernel 1: leaf softmax -> duplicated pairs ----------------
__global__ __launch_bounds__(256)
void prep_leaf_kernel(const float* __restrict__ leaf, float* __restrict__ lp) {
    int idx = blockIdx.x * blockDim.x + threadIdx.x;   // t*128 + l
    if (idx >= T_ * L_) return;
    const float* in = leaf + (size_t)idx * C_;
    float v[C_];
    float m = -1e30f;
    #pragma unroll
    for (int c = 0; c < C_; c++) { v[c] = in[c]; m = fmaxf(m, v[c]); }
    float sum = 0.f;
    #pragma unroll
    for (int c = 0; c < C_; c++) { v[c] = expf(v[c] - m); sum += v[c]; }
    float inv = 1.0f / sum;
    float* o = lp + (size_t)idx * LPROW;
    #pragma unroll
    for (int c = 0; c < C_; c++) { float p = v[c] * inv; o[2*c] = p; o[2*c+1] = p; }
    o[20] = 0.f; o[21] = 0.f; o[22] = 0.f; o[23] = 0.f;
}

// ---------------- kernel 2: MLP attention, smem-staged transposed store -----
__global__ __launch_bounds__(256)
void attn_kernel(const float* __restrict__ x,  const float* __restrict__ W1,
                 const float* __restrict__ b1, const float* __restrict__ W2,
                 const float* __restrict__ b2, float* __restrict__ attn_out) {
    __shared__ float sx[8][128];
    __shared__ float sh[8][64];
    __shared__ float sout[128][9];      // [t][b within block], pad 9
    int w = threadIdx.x >> 5, lane = threadIdx.x & 31;
    int b0 = blockIdx.x * 8;
    int b = b0 + w;

    #pragma unroll
    for (int k = 0; k < 4; k++) sx[w][lane + 32 * k] = x[(size_t)b * I_ + lane + 32 * k];
    __syncwarp();

    float h0 = b1[lane], h1 = b1[lane + 32];
    #pragma unroll 4
    for (int i = 0; i < I_; i++) {
        float xi = sx[w][i];
        h0 = fmaf(xi, W1[i * 64 + lane],      h0);
        h1 = fmaf(xi, W1[i * 64 + lane + 32], h1);
    }
    sh[w][lane]      = fmaxf(h0, 0.f);
    sh[w][lane + 32] = fmaxf(h1, 0.f);
    __syncwarp();

    float lg[4];
    #pragma unroll
    for (int k = 0; k < 4; k++) lg[k] = b2[lane + 32 * k];
    #pragma unroll 4
    for (int j = 0; j < 64; j++) {
        float hj = sh[w][j];
        #pragma unroll
        for (int k = 0; k < 4; k++)
            lg[k] = fmaf(hj, W2[j * T_ + lane + 32 * k], lg[k]);
    }
    float m = fmaxf(fmaxf(lg[0], lg[1]), fmaxf(lg[2], lg[3]));
    #pragma unroll
    for (int o = 16; o; o >>= 1) m = fmaxf(m, __shfl_xor_sync(0xffffffffu, m, o));
    float sum = 0.f;
    #pragma unroll
    for (int k = 0; k < 4; k++) { lg[k] = expf(lg[k] - m); sum += lg[k]; }
    #pragma unroll
    for (int o = 16; o; o >>= 1) sum += __shfl_xor_sync(0xffffffffu, sum, o);
    float inv = 1.0f / sum;
    #pragma unroll
    for (int k = 0; k < 4; k++) sout[lane + 32 * k][w] = lg[k] * inv;
    __syncthreads();

    // store [t][8 b] chunks: lanes j fastest -> 32B segments, 4 wf/instr
    for (int i = threadIdx.x; i < 128 * 8; i += 256) {
        int t = i >> 3, j = i & 7;
        attn_out[(size_t)t * B_ + b0 + j] = sout[t][j];
    }
}

// ---------------- kernel 3: z GEMM (packed f32x2) + softsign, staged store ---
// tile: M=32 b-rows x N=128, K=128 resident. thread: 4 m (packed dup A) x 4 n.
#define KZ_SMEM_FLOATS (128 * 68 + 128 * 132)
__global__ __launch_bounds__(256)
void kz_kernel(const float* __restrict__ x, const float* __restrict__ fm,
               const float* __restrict__ thr, float* __restrict__ s_out) {
    extern __shared__ float smz[];
    float* Asd = smz;                 // [128][68] (also reused as output stage)
    float* Bs  = smz + 128 * 68;      // [128][132]
    int tid = threadIdx.x;
    int b0 = blockIdx.x * 32;
    int n0 = blockIdx.y * 128;

    for (int idx = tid; idx < 32 * 32; idx += 256) {
        int m = idx >> 5, k4 = idx & 31;
        float4 xv = *(const float4*)&x[(size_t)(b0 + m) * I_ + 4 * k4];
        *(u64x*)&Asd[(4 * k4 + 0) * 68 + 2 * m] = pk2(xv.x, xv.x);
        *(u64x*)&Asd[(4 * k4 + 1) * 68 + 2 * m] = pk2(xv.y, xv.y);
        *(u64x*)&Asd[(4 * k4 + 2) * 68 + 2 * m] = pk2(xv.z, xv.z);
        *(u64x*)&Asd[(4 * k4 + 3) * 68 + 2 * m] = pk2(xv.w, xv.w);
    }
    for (int idx = tid; idx < 128 * 32; idx += 256) {
        int n = idx >> 5, k4 = idx & 31;
        float4 fv = *(const float4*)&fm[(size_t)(n0 + n) * I_ + 4 * k4];
        Bs[(4 * k4 + 0) * 132 + n] = fv.x;
        Bs[(4 * k4 + 1) * 132 + n] = fv.y;
        Bs[(4 * k4 + 2) * 132 + n] = fv.z;
        Bs[(4 * k4 + 3) * 132 + n] = fv.w;
    }
    __syncthreads();

    int tn = tid & 31, tb = tid >> 5;       // tb uniform in warp -> A broadcast
    u64x acc[4][2];
    #pragma unroll
    for (int i = 0; i < 4; i++) { acc[i][0] = 0; acc[i][1] = 0; }

    const float* aP = Asd + 8 * tb;
    const float* bP = Bs + 4 * tn;
    #pragma unroll 8
    for (int k = 0; k < 128; k++) {
        double2 ad0 = *(const double2*)(aP + k * 68);
        double2 ad1 = *(const double2*)(aP + k * 68 + 4);
        double2 bd  = *(const double2*)(bP + k * 132);
        u64x b01 = d2u(bd.x), b23 = d2u(bd.y);
        u64x a0 = d2u(ad0.x), a1 = d2u(ad0.y), a2 = d2u(ad1.x), a3 = d2u(ad1.y);
        acc[0][0] = fma2_(a0, b01, acc[0][0]); acc[0][1] = fma2_(a0, b23, acc[0][1]);
        acc[1][0] = fma2_(a1, b01, acc[1][0]); acc[1][1] = fma2_(a1, b23, acc[1][1]);
        acc[2][0] = fma2_(a2, b01, acc[2][0]); acc[2][1] = fma2_(a2, b23, acc[2][1]);
        acc[3][0] = fma2_(a3, b01, acc[3][0]); acc[3][1] = fma2_(a3, b23, acc[3][1]);
    }

    float av[4][4];
    #pragma unroll
    for (int i = 0; i < 4; i++) {
        upk2(av[i][0], av[i][1], acc[i][0]);
        upk2(av[i][2], av[i][3], acc[i][1]);
    }
    __syncthreads();                        // done reading Asd/Bs
    float* stage = Asd;                     // [n=128][m=32] pad 33
    #pragma unroll
    for (int jn = 0; jn < 4; jn++) {
        int n = tn * 4 + jn;
        float th = thr[n0 + n];
        #pragma unroll
        for (int u = 0; u < 4; u++) {
            float z = av[u][jn] - th;
            stage[n * 33 + tb * 4 + u] =
                fmaf(0.5f, __fdividef(z, 1.0f + fabsf(z)), 0.5f);
        }
    }
    __syncthreads();
    // coalesced store: warp per row, lane = b
    int w = tid >> 5, lane = tid & 31;
    #pragma unroll
    for (int i = 0; i < 16; i++) {
        int n = w * 16 + i;
        s_out[(size_t)(n0 + n) * B_ + b0 + lane] = stage[n * 33 + lane];
    }
}

// ---------------- kernel 4: leaf products + mix, 4 b per lane ----------------
// grid (B/128, NSPLIT). block 128 thr = 4 warps. warp w: 4 trees; lane: 4 b's.
#define KMIX_SMEM_FLOATS (4 * L_ * LPROW)     // 4 warp slabs x 128 leaves x 24
__global__ __launch_bounds__(128)
void kmix_kernel(const float* __restrict__ s_in, const float* __restrict__ attn,
                 const float* __restrict__ lp, float* __restrict__ part) {
    extern __shared__ float smm[];
    int w = threadIdx.x >> 5, lane = threadIdx.x & 31;
    int bbase = blockIdx.x * 128;
    int ts = blockIdx.y;

    const u64x ONE2 = 0x3f8000003f800000ULL;
    const u64x NEG2 = 0xbf800000bf800000ULL;

    u64x acc[C_][2];
    #pragma unroll
    for (int c = 0; c < C_; c++) { acc[c][0] = 0; acc[c][1] = 0; }

    float* myLP = smm + w * (L_ * LPROW);

    for (int tt = 0; tt < 4; tt++) {
        int t = ts * 16 + w * 4 + tt;
        __syncwarp();
        const float4* src = (const float4*)(lp + (size_t)t * (L_ * LPROW));
        float4* dst = (float4*)myLP;
        #pragma unroll
        for (int k = 0; k < 24; k++) dst[lane + 32 * k] = src[lane + 32 * k];
        __syncwarp();

        // packed s, (1-s) for two b-pairs: (lane, lane+32) and (lane+64, lane+96)
        u64x sv0[D_], mv0[D_], sv1[D_], mv1[D_];
        const float* sp = s_in + (size_t)(t * D_) * B_ + bbase + lane;
        #pragma unroll
        for (int d = 0; d < D_; d++) {
            const float* q = sp + (size_t)d * B_;
            sv0[d] = pk2(q[0],  q[32]);
            sv1[d] = pk2(q[64], q[96]);
            mv0[d] = fma2_(sv0[d], NEG2, ONE2);
            mv1[d] = fma2_(sv1[d], NEG2, ONE2);
        }
        const float* ap = attn + (size_t)t * B_ + bbase + lane;
        u64x a0 = pk2(ap[0],  ap[32]);
        u64x a1 = pk2(ap[64], ap[96]);

        // pLow bits 0..2 (both pairs)
        u64x pl0[8], pl1[8];
        pl0[0] = sv0[0]; pl0[1] = mv0[0];
        pl1[0] = sv1[0]; pl1[1] = mv1[0];
        pl0[2] = mul2_(pl0[0], mv0[1]); pl0[3] = mul2_(pl0[1], mv0[1]);
        pl1[2] = mul2_(pl1[0], mv1[1]); pl1[3] = mul2_(pl1[1], mv1[1]);
        pl0[0] = mul2_(pl0[0], sv0[1]); pl0[1] = mul2_(pl0[1], sv0[1]);
        pl1[0] = mul2_(pl1[0], sv1[1]); pl1[1] = mul2_(pl1[1], sv1[1]);
        pl0[4] = mul2_(pl0[0], mv0[2]); pl0[5] = mul2_(pl0[1], mv0[2]);
        pl0[6] = mul2_(pl0[2], mv0[2]); pl0[7] = mul2_(pl0[3], mv0[2]);
        pl1[4] = mul2_(pl1[0], mv1[2]); pl1[5] = mul2_(pl1[1], mv1[2]);
        pl1[6] = mul2_(pl1[2], mv1[2]); pl1[7] = mul2_(pl1[3], mv1[2]);
        pl0[0] = mul2_(pl0[0], sv0[2]); pl0[1] = mul2_(pl0[1], sv0[2]);
        pl0[2] = mul2_(pl0[2], sv0[2]); pl0[3] = mul2_(pl0[3], sv0[2]);
        pl1[0] = mul2_(pl1[0], sv1[2]); pl1[1] = mul2_(pl1[1], sv1[2]);
        pl1[2] = mul2_(pl1[2], sv1[2]); pl1[3] = mul2_(pl1[3], sv1[2]);
        // pHigh bits 3..6, attention folded at level 0 (both pairs)
        u64x ph0[16], ph1[16];
        ph0[0] = mul2_(a0, sv0[3]); ph0[1] = mul2_(a0, mv0[3]);
        ph1[0] = mul2_(a1, sv1[3]); ph1[1] = mul2_(a1, mv1[3]);
        ph0[2] = mul2_(ph0[0], mv0[4]); ph0[3] = mul2_(ph0[1], mv0[4]);
        ph1[2] = mul2_(ph1[0], mv1[4]); ph1[3] = mul2_(ph1[1], mv1[4]);
        ph0[0] = mul2_(ph0[0], sv0[4]); ph0[1] = mul2_(ph0[1], sv0[4]);
        ph1[0] = mul2_(ph1[0], sv1[4]); ph1[1] = mul2_(ph1[1], sv1[4]);
        ph0[4] = mul2_(ph0[0], mv0[5]); ph0[5] = mul2_(ph0[1], mv0[5]);
        ph0[6] = mul2_(ph0[2], mv0[5]); ph0[7] = mul2_(ph0[3], mv0[5]);
        ph1[4] = mul2_(ph1[0], mv1[5]); ph1[5] = mul2_(ph1[1], mv1[5]);
        ph1[6] = mul2_(ph1[2], mv1[5]); ph1[7] = mul2_(ph1[3], mv1[5]);
        ph0[0] = mul2_(ph0[0], sv0[5]); ph0[1] = mul2_(ph0[1], sv0[5]);
        ph0[2] = mul2_(ph0[2], sv0[5]); ph0[3] = mul2_(ph0[3], sv0[5]);
        ph1[0] = mul2_(ph1[0], sv1[5]); ph1[1] = mul2_(ph1[1], sv1[5]);
        ph1[2] = mul2_(ph1[2], sv1[5]); ph1[3] = mul2_(ph1[3], sv1[5]);
        #pragma unroll
        for (int j = 0; j < 8; j++) { ph0[8+j] = mul2_(ph0[j], mv0[6]);
                                      ph1[8+j] = mul2_(ph1[j], mv1[6]); }
        #pragma unroll
        for (int j = 0; j < 8; j++) { ph0[j] = mul2_(ph0[j], sv0[6]);
                                      ph1[j] = mul2_(ph1[j], sv1[6]); }

        // mix: per leaf 5x broadcast LDS.128 feed 20 FFMA2 + 2 MUL2
        #pragma unroll
        for (int m = 0; m < 16; m++) {
            u64x pm0 = ph0[m], pm1 = ph1[m];
            #pragma unroll
            for (int j = 0; j < 8; j++) {
                const float* Lr = myLP + (m * 8 + j) * LPROW;
                double2 L0 = *(const double2*)(Lr);
                double2 L1 = *(const double2*)(Lr + 4);
                double2 L2 = *(const double2*)(Lr + 8);
                double2 L3 = *(const double2*)(Lr + 12);
                double2 L4 = *(const double2*)(Lr + 16);
                u64x q0 = mul2_(pl0[j], pm0);
                u64x q1 = mul2_(pl1[j], pm1);
                acc[0][0] = fma2_(q0, d2u(L0.x), acc[0][0]);
                acc[0][1] = fma2_(q1, d2u(L0.x), acc[0][1]);
                acc[1][0] = fma2_(q0, d2u(L0.y), acc[1][0]);
                acc[1][1] = fma2_(q1, d2u(L0.y), acc[1][1]);
                acc[2][0] = fma2_(q0, d2u(L1.x), acc[2][0]);
                acc[2][1] = fma2_(q1, d2u(L1.x), acc[2][1]);
                acc[3][0] = fma2_(q0, d2u(L1.y), acc[3][0]);
                acc[3][1] = fma2_(q1, d2u(L1.y), acc[3][1]);
                acc[4][0] = fma2_(q0, d2u(L2.x), acc[4][0]);
                acc[4][1] = fma2_(q1, d2u(L2.x), acc[4][1]);
                acc[5][0] = fma2_(q0, d2u(L2.y), acc[5][0]);
                acc[5][1] = fma2_(q1, d2u(L2.y), acc[5][1]);
                acc[6][0] = fma2_(q0, d2u(L3.x), acc[6][0]);
                acc[6][1] = fma2_(q1, d2u(L3.x), acc[6][1]);
                acc[7][0] = fma2_(q0, d2u(L3.y), acc[7][0]);
                acc[7][1] = fma2_(q1, d2u(L3.y), acc[7][1]);
                acc[8][0] = fma2_(q0, d2u(L4.x), acc[8][0]);
                acc[8][1] = fma2_(q1, d2u(L4.x), acc[8][1]);
                acc[9][0] = fma2_(q0, d2u(L4.y), acc[9][0]);
                acc[9][1] = fma2_(q1, d2u(L4.y), acc[9][1]);
            }
        }
    }

    // in-block reduction over the 4 warps (different trees); reuse slab smem
    __syncthreads();
    u64x* sr = (u64x*)smm;                 // [4][32][10][2] u64
    #pragma unroll
    for (int c = 0; c < C_; c++) {
        sr[((w * 32 + lane) * C_ + c) * 2 + 0] = acc[c][0];
        sr[((w * 32 + lane) * C_ + c) * 2 + 1] = acc[c][1];
    }
    __syncthreads();
    {
        int bl = threadIdx.x;              // local b 0..127
        int pp  = bl >> 6;                 // which pair
        int sel = (bl >> 5) & 1;           // lo/hi within pair
        int ln  = bl & 31;
        const float* srf = (const float*)sr;
        float v[C_];
        #pragma unroll
        for (int c = 0; c < C_; c++) {
            float s = 0.f;
            #pragma unroll
            for (int ww = 0; ww < 4; ww++)
                s += srf[(((ww * 32 + ln) * C_ + c) * 2 + pp) * 2 + sel];
            v[c] = s;
        }
        float* o = part + ((size_t)ts * B_ + bbase + bl) * C_;
        #pragma unroll
        for (int c = 0; c < C_; c++) o[c] = v[c];
    }
}

// ---------------- kernel 5: sum the NSPLIT tree-split partials ----------------
__global__ __launch_bounds__(256)
void reduce_kernel(const float* __restrict__ part, float* __restrict__ out) {
    int i = blockIdx.x * blockDim.x + threadIdx.x;
    if (i >= B_ * C_) return;
    float s = 0.f;
    #pragma unroll
    for (int k = 0; k < NSPLIT; k++) s += part[(size_t)k * B_ * C_ + i];
    out[i] = s;
}

// ---------------- launcher ----------------
extern "C" void kernel_launch(void* const* d_in, const int* in_sizes, int n_in,
                              void* d_out, int out_size) {
    const float* x    = (const float*)d_in[0];
    const float* fm   = (const float*)d_in[1];
    const float* thr  = (const float*)d_in[2];
    const float* leaf = (const float*)d_in[3];
    const float* W1   = (const float*)d_in[4];
    const float* b1   = (const float*)d_in[5];
    const float* W2   = (const float*)d_in[6];
    const float* b2   = (const float*)d_in[7];
    float* out = (float*)d_out;

    float *gLP, *gAt, *gS, *gP;
    cudaGetSymbolAddress((void**)&gLP, g_LP);
    cudaGetSymbolAddress((void**)&gAt, g_attn);
    cudaGetSymbolAddress((void**)&gS,  g_s);
    cudaGetSymbolAddress((void**)&gP,  g_part);

    cudaFuncSetAttribute(kz_kernel,   cudaFuncAttributeMaxDynamicSharedMemorySize,
                         KZ_SMEM_FLOATS * 4);
    cudaFuncSetAttribute(kmix_kernel, cudaFuncAttributeMaxDynamicSharedMemorySize,
                         KMIX_SMEM_FLOATS * 4);
    (void)in_sizes; (void)n_in; (void)out_size;

    prep_leaf_kernel<<<(T_ * L_ + 255) / 256, 256>>>(leaf, gLP);
    attn_kernel<<<B_ / 8, 256>>>(x, W1, b1, W2, b2, gAt);
    kz_kernel<<<dim3(B_ / 32, TD_ / 128), 256, KZ_SMEM_FLOATS * 4>>>(x, fm, thr, gS);
    kmix_kernel<<<dim3(B_ / 128, NSPLIT), 128, KMIX_SMEM_FLOATS * 4>>>(gS, gAt, gLP, gP);
    reduce_kernel<<<(B_ * C_ + 255) / 256, 256>>>(gP, out);
}

// round 7
// speedup vs baseline: 1.4643x; 1.3069x over previous
#include <cuda_runtime.h>
#include <math.h>

// Problem constants
#define B_  8192
#define T_  128
#define D_  7
#define I_  128
#define C_  10
#define L_  128
#define TD_ 896          // T_*D_
#define LPROW 24         // duplicated leafP row: 10 classes x {v,v} = 20, pad to 24
#define NSPLIT 16        // kmix tree splits

typedef unsigned long long u64x;

__device__ __forceinline__ u64x pk2(float lo, float hi) {
    u64x r; asm("mov.b64 %0, {%1, %2};" : "=l"(r) : "f"(lo), "f"(hi)); return r;
}
__device__ __forceinline__ void upk2(float& lo, float& hi, u64x v) {
    asm("mov.b64 {%0, %1}, %2;" : "=f"(lo), "=f"(hi) : "l"(v));
}
__device__ __forceinline__ u64x mul2_(u64x a, u64x b) {
    u64x d; asm("mul.rn.f32x2 %0, %1, %2;" : "=l"(d) : "l"(a), "l"(b)); return d;
}
__device__ __forceinline__ u64x fma2_(u64x a, u64x b, u64x c) {
    u64x d; asm("fma.rn.f32x2 %0, %1, %2, %3;" : "=l"(d) : "l"(a), "l"(b), "l"(c)); return d;
}
__device__ __forceinline__ u64x d2u(double v) { return (u64x)__double_as_longlong(v); }

// ---------------- scratch (__device__ globals; no allocation) ----------------
__device__ float g_LP[T_ * L_ * LPROW];            // softmaxed leaf probs, duplicated pairs
__device__ float g_attn[T_ * B_];                  // attention, TRANSPOSED [t][b]
__device__ float g_s[(size_t)TD_ * B_];            // softsign(z), TRANSPOSED [t*7+d][b]
__device__ float g_part[NSPLIT * B_ * C_];         // kmix partials

// ---------------- kernel 1: leaf softmax -> duplicated pairs ----------------
__global__ __launch_bounds__(256)
void prep_leaf_kernel(const float* __restrict__ leaf, float* __restrict__ lp) {
    int idx = blockIdx.x * blockDim.x + threadIdx.x;   // t*128 + l
    if (idx >= T_ * L_) return;
    const float* in = leaf + (size_t)idx * C_;
    float v[C_];
    float m = -1e30f;
    #pragma unroll
    for (int c = 0; c < C_; c++) { v[c] = in[c]; m = fmaxf(m, v[c]); }
    float sum = 0.f;
    #pragma unroll
    for (int c = 0; c < C_; c++) { v[c] = expf(v[c] - m); sum += v[c]; }
    float inv = 1.0f / sum;
    float* o = lp + (size_t)idx * LPROW;
    #pragma unroll
    for (int c = 0; c < C_; c++) { float p = v[c] * inv; o[2*c] = p; o[2*c+1] = p; }
    o[20] = 0.f; o[21] = 0.f; o[22] = 0.f; o[23] = 0.f;
}

// ---------------- kernel 2: MLP attention, W1/W2 staged in smem -------------
// block = 512 threads = 16 warps = 16 rows b. W1+W2 read once per block.
__global__ __launch_bounds__(512)
void attn_kernel(const float* __restrict__ x,  const float* __restrict__ W1,
                 const float* __restrict__ b1, const float* __restrict__ W2,
                 const float* __restrict__ b2, float* __restrict__ attn_out) {
    extern __shared__ float sma[];
    float* sW1  = sma;                   // 8192
    float* sW2  = sma + 8192;            // 8192
    float* sx   = sma + 16384;           // [16][128]
    float* sh   = sma + 16384 + 2048;    // [16][64]
    float* sout = sma + 16384 + 3072;    // [128][17]
    int w = threadIdx.x >> 5, lane = threadIdx.x & 31;
    int b0 = blockIdx.x * 16;
    int b = b0 + w;

    for (int i = threadIdx.x; i < 2048; i += 512) {
        ((float4*)sW1)[i] = ((const float4*)W1)[i];
        ((float4*)sW2)[i] = ((const float4*)W2)[i];
    }
    #pragma unroll
    for (int k = 0; k < 4; k++)
        sx[w * 128 + lane + 32 * k] = x[(size_t)b * I_ + lane + 32 * k];
    __syncthreads();

    float h0 = b1[lane], h1 = b1[lane + 32];
    #pragma unroll 4
    for (int i = 0; i < I_; i++) {
        float xi = sx[w * 128 + i];
        h0 = fmaf(xi, sW1[i * 64 + lane],      h0);
        h1 = fmaf(xi, sW1[i * 64 + lane + 32], h1);
    }
    sh[w * 64 + lane]      = fmaxf(h0, 0.f);
    sh[w * 64 + lane + 32] = fmaxf(h1, 0.f);
    __syncwarp();

    float lg[4];
    #pragma unroll
    for (int k = 0; k < 4; k++) lg[k] = b2[lane + 32 * k];
    #pragma unroll 4
    for (int j = 0; j < 64; j++) {
        float hj = sh[w * 64 + j];
        #pragma unroll
        for (int k = 0; k < 4; k++)
            lg[k] = fmaf(hj, sW2[j * T_ + lane + 32 * k], lg[k]);
    }
    float m = fmaxf(fmaxf(lg[0], lg[1]), fmaxf(lg[2], lg[3]));
    #pragma unroll
    for (int o = 16; o; o >>= 1) m = fmaxf(m, __shfl_xor_sync(0xffffffffu, m, o));
    float sum = 0.f;
    #pragma unroll
    for (int k = 0; k < 4; k++) { lg[k] = expf(lg[k] - m); sum += lg[k]; }
    #pragma unroll
    for (int o = 16; o; o >>= 1) sum += __shfl_xor_sync(0xffffffffu, sum, o);
    float inv = 1.0f / sum;
    #pragma unroll
    for (int k = 0; k < 4; k++) sout[(lane + 32 * k) * 17 + w] = lg[k] * inv;
    __syncthreads();

    for (int i = threadIdx.x; i < 128 * 16; i += 512) {
        int t = i >> 4, j = i & 15;
        attn_out[(size_t)t * B_ + b0 + j] = sout[t * 17 + j];
    }
}
#define ATTN_SMEM_FLOATS (16384 + 3072 + 128 * 17)

// ---------------- kernel 3: z GEMM (packed f32x2) + softsign ----------------
// tile 128b x 128n, K chunks of 32. 256 threads = 16x16, micro 8m x 8n.
// smem overlay: Ad [32][260] @0 (m duplicated pairs), Bs [32][132] @8320;
// stage [128][132] reuses the region after the mainloop.
#define KZ_SMEM_FLOATS (128 * 132)
__global__ __launch_bounds__(256)
void kz_kernel(const float* __restrict__ x, const float* __restrict__ fm,
               const float* __restrict__ thr, float* __restrict__ s_out) {
    extern __shared__ float smz[];
    float* Ad = smz;                  // [32][260]
    float* Bs = smz + 32 * 260;       // [32][132]
    int tid = threadIdx.x;
    int b0 = blockIdx.x * 128;
    int n0 = blockIdx.y * 128;
    int tm = tid >> 4, tn = tid & 15;

    u64x acc[8][4];
    #pragma unroll
    for (int i = 0; i < 8; i++)
        #pragma unroll
        for (int j = 0; j < 4; j++) acc[i][j] = 0;

    for (int kc = 0; kc < 4; kc++) {
        __syncthreads();
        for (int idx = tid; idx < 1024; idx += 256) {
            int m = idx >> 3, k4 = idx & 7;
            float4 xv = *(const float4*)&x[(size_t)(b0 + m) * I_ + kc * 32 + 4 * k4];
            *(u64x*)&Ad[(4 * k4 + 0) * 260 + 2 * m] = pk2(xv.x, xv.x);
            *(u64x*)&Ad[(4 * k4 + 1) * 260 + 2 * m] = pk2(xv.y, xv.y);
            *(u64x*)&Ad[(4 * k4 + 2) * 260 + 2 * m] = pk2(xv.z, xv.z);
            *(u64x*)&Ad[(4 * k4 + 3) * 260 + 2 * m] = pk2(xv.w, xv.w);
        }
        for (int idx = tid; idx < 1024; idx += 256) {
            int n = idx >> 3, k4 = idx & 7;
            float4 fv = *(const float4*)&fm[(size_t)(n0 + n) * I_ + kc * 32 + 4 * k4];
            Bs[(4 * k4 + 0) * 132 + n] = fv.x;
            Bs[(4 * k4 + 1) * 132 + n] = fv.y;
            Bs[(4 * k4 + 2) * 132 + n] = fv.z;
            Bs[(4 * k4 + 3) * 132 + n] = fv.w;
        }
        __syncthreads();

        #pragma unroll 4
        for (int k = 0; k < 32; k++) {
            const float* aP = Ad + k * 260 + tm * 16;
            const float* bP = Bs + k * 132 + tn * 8;
            double2 A0 = *(const double2*)(aP);
            double2 A1 = *(const double2*)(aP + 4);
            double2 A2 = *(const double2*)(aP + 8);
            double2 A3 = *(const double2*)(aP + 12);
            double2 B0 = *(const double2*)(bP);
            double2 B1 = *(const double2*)(bP + 4);
            u64x a[8] = { d2u(A0.x), d2u(A0.y), d2u(A1.x), d2u(A1.y),
                          d2u(A2.x), d2u(A2.y), d2u(A3.x), d2u(A3.y) };
            u64x bb[4] = { d2u(B0.x), d2u(B0.y), d2u(B1.x), d2u(B1.y) };
            #pragma unroll
            for (int i = 0; i < 8; i++)
                #pragma unroll
                for (int j = 0; j < 4; j++)
                    acc[i][j] = fma2_(a[i], bb[j], acc[i][j]);
        }
    }

    __syncthreads();
    float* stage = smz;               // [n=128][132]
    float thv[8];
    #pragma unroll
    for (int j = 0; j < 8; j++) thv[j] = thr[n0 + tn * 8 + j];
    #pragma unroll
    for (int i = 0; i < 8; i++) {
        int m = tm * 8 + i;
        #pragma unroll
        for (int j = 0; j < 4; j++) {
            float lo, hi; upk2(lo, hi, acc[i][j]);
            float z0 = lo - thv[2 * j], z1 = hi - thv[2 * j + 1];
            stage[(tn * 8 + 2 * j)     * 132 + m] =
                fmaf(0.5f, __fdividef(z0, 1.0f + fabsf(z0)), 0.5f);
            stage[(tn * 8 + 2 * j + 1) * 132 + m] =
                fmaf(0.5f, __fdividef(z1, 1.0f + fabsf(z1)), 0.5f);
        }
    }
    __syncthreads();
    int w = tid >> 5, lane = tid & 31;
    #pragma unroll
    for (int i = 0; i < 16; i++) {
        int n = w * 16 + i;
        float4 v = *(const float4*)&stage[n * 132 + lane * 4];
        *(float4*)&s_out[(size_t)(n0 + n) * B_ + b0 + lane * 4] = v;
    }
}

// ---------------- kernel 4: leaf products + mix, 4 b per lane ----------------
// grid (B/128, NSPLIT). block 128 = 4 warps; warp: 2 trees; lane: 4 b's.
// register-compact: pm streamed from ph4[4] x f[4] basis.
#define KMIX_SMEM_FLOATS (4 * L_ * LPROW)
__global__ __launch_bounds__(128, 4)
void kmix_kernel(const float* __restrict__ s_in, const float* __restrict__ attn,
                 const float* __restrict__ lp, float* __restrict__ part) {
    extern __shared__ float smm[];
    int w = threadIdx.x >> 5, lane = threadIdx.x & 31;
    int bbase = blockIdx.x * 128;
    int ts = blockIdx.y;

    const u64x ONE2 = 0x3f8000003f800000ULL;
    const u64x NEG2 = 0xbf800000bf800000ULL;

    u64x acc[C_][2];
    #pragma unroll
    for (int c = 0; c < C_; c++) { acc[c][0] = 0; acc[c][1] = 0; }

    float* myLP = smm + w * (L_ * LPROW);

    for (int tt = 0; tt < 2; tt++) {
        int t = ts * 8 + w * 2 + tt;
        __syncwarp();
        const float4* src = (const float4*)(lp + (size_t)t * (L_ * LPROW));
        float4* dst = (float4*)myLP;
        #pragma unroll
        for (int k = 0; k < 24; k++) dst[lane + 32 * k] = src[lane + 32 * k];
        __syncwarp();

        u64x sv0[D_], mv0[D_], sv1[D_], mv1[D_];
        const float* sp = s_in + (size_t)(t * D_) * B_ + bbase + lane;
        #pragma unroll
        for (int d = 0; d < D_; d++) {
            const float* q = sp + (size_t)d * B_;
            sv0[d] = pk2(q[0],  q[32]);
            sv1[d] = pk2(q[64], q[96]);
            mv0[d] = fma2_(sv0[d], NEG2, ONE2);
            mv1[d] = fma2_(sv1[d], NEG2, ONE2);
        }
        const float* ap = attn + (size_t)t * B_ + bbase + lane;
        u64x a0 = pk2(ap[0],  ap[32]);
        u64x a1 = pk2(ap[64], ap[96]);

        // pLow bits 0..2
        u64x pl0[8], pl1[8];
        pl0[0] = sv0[0]; pl0[1] = mv0[0];
        pl1[0] = sv1[0]; pl1[1] = mv1[0];
        pl0[2] = mul2_(pl0[0], mv0[1]); pl0[3] = mul2_(pl0[1], mv0[1]);
        pl1[2] = mul2_(pl1[0], mv1[1]); pl1[3] = mul2_(pl1[1], mv1[1]);
        pl0[0] = mul2_(pl0[0], sv0[1]); pl0[1] = mul2_(pl0[1], sv0[1]);
        pl1[0] = mul2_(pl1[0], sv1[1]); pl1[1] = mul2_(pl1[1], sv1[1]);
        pl0[4] = mul2_(pl0[0], mv0[2]); pl0[5] = mul2_(pl0[1], mv0[2]);
        pl0[6] = mul2_(pl0[2], mv0[2]); pl0[7] = mul2_(pl0[3], mv0[2]);
        pl1[4] = mul2_(pl1[0], mv1[2]); pl1[5] = mul2_(pl1[1], mv1[2]);
        pl1[6] = mul2_(pl1[2], mv1[2]); pl1[7] = mul2_(pl1[3], mv1[2]);
        pl0[0] = mul2_(pl0[0], sv0[2]); pl0[1] = mul2_(pl0[1], sv0[2]);
        pl0[2] = mul2_(pl0[2], sv0[2]); pl0[3] = mul2_(pl0[3], sv0[2]);
        pl1[0] = mul2_(pl1[0], sv1[2]); pl1[1] = mul2_(pl1[1], sv1[2]);
        pl1[2] = mul2_(pl1[2], sv1[2]); pl1[3] = mul2_(pl1[3], sv1[2]);

        // ph4 basis: bits 3,4 with attn folded; f basis: bits 5,6
        u64x t00 = mul2_(a0, sv0[3]), t01 = mul2_(a0, mv0[3]);
        u64x t10 = mul2_(a1, sv1[3]), t11 = mul2_(a1, mv1[3]);
        u64x ph40[4], ph41[4], f0[4], f1[4];
        ph40[0] = mul2_(t00, sv0[4]); ph40[1] = mul2_(t01, sv0[4]);
        ph40[2] = mul2_(t00, mv0[4]); ph40[3] = mul2_(t01, mv0[4]);
        ph41[0] = mul2_(t10, sv1[4]); ph41[1] = mul2_(t11, sv1[4]);
        ph41[2] = mul2_(t10, mv1[4]); ph41[3] = mul2_(t11, mv1[4]);
        f0[0] = mul2_(sv0[5], sv0[6]); f0[1] = mul2_(mv0[5], sv0[6]);
        f0[2] = mul2_(sv0[5], mv0[6]); f0[3] = mul2_(mv0[5], mv0[6]);
        f1[0] = mul2_(sv1[5], sv1[6]); f1[1] = mul2_(mv1[5], sv1[6]);
        f1[2] = mul2_(sv1[5], mv1[6]); f1[3] = mul2_(mv1[5], mv1[6]);

        // mix: per leaf 5x broadcast LDS.128 feed 20 FFMA2 + 2 MUL2
        #pragma unroll
        for (int m = 0; m < 16; m++) {
            u64x pm0 = mul2_(ph40[m & 3], f0[m >> 2]);
            u64x pm1 = mul2_(ph41[m & 3], f1[m >> 2]);
            #pragma unroll
            for (int j = 0; j < 8; j++) {
                const float* Lr = myLP + (m * 8 + j) * LPROW;
                double2 L0 = *(const double2*)(Lr);
                double2 L1 = *(const double2*)(Lr + 4);
                double2 L2 = *(const double2*)(Lr + 8);
                double2 L3 = *(const double2*)(Lr + 12);
                double2 L4 = *(const double2*)(Lr + 16);
                u64x q0 = mul2_(pl0[j], pm0);
                u64x q1 = mul2_(pl1[j], pm1);
                acc[0][0] = fma2_(q0, d2u(L0.x), acc[0][0]);
                acc[0][1] = fma2_(q1, d2u(L0.x), acc[0][1]);
                acc[1][0] = fma2_(q0, d2u(L0.y), acc[1][0]);
                acc[1][1] = fma2_(q1, d2u(L0.y), acc[1][1]);
                acc[2][0] = fma2_(q0, d2u(L1.x), acc[2][0]);
                acc[2][1] = fma2_(q1, d2u(L1.x), acc[2][1]);
                acc[3][0] = fma2_(q0, d2u(L1.y), acc[3][0]);
                acc[3][1] = fma2_(q1, d2u(L1.y), acc[3][1]);
                acc[4][0] = fma2_(q0, d2u(L2.x), acc[4][0]);
                acc[4][1] = fma2_(q1, d2u(L2.x), acc[4][1]);
                acc[5][0] = fma2_(q0, d2u(L2.y), acc[5][0]);
                acc[5][1] = fma2_(q1, d2u(L2.y), acc[5][1]);
                acc[6][0] = fma2_(q0, d2u(L3.x), acc[6][0]);
                acc[6][1] = fma2_(q1, d2u(L3.x), acc[6][1]);
                acc[7][0] = fma2_(q0, d2u(L3.y), acc[7][0]);
                acc[7][1] = fma2_(q1, d2u(L3.y), acc[7][1]);
                acc[8][0] = fma2_(q0, d2u(L4.x), acc[8][0]);
                acc[8][1] = fma2_(q1, d2u(L4.x), acc[8][1]);
                acc[9][0] = fma2_(q0, d2u(L4.y), acc[9][0]);
                acc[9][1] = fma2_(q1, d2u(L4.y), acc[9][1]);
            }
        }
    }

    // in-block reduction over the 4 warps (different trees); reuse slab smem
    __syncthreads();
    u64x* sr = (u64x*)smm;                 // [4][32][10][2] u64
    #pragma unroll
    for (int c = 0; c < C_; c++) {
        sr[((w * 32 + lane) * C_ + c) * 2 + 0] = acc[c][0];
        sr[((w * 32 + lane) * C_ + c) * 2 + 1] = acc[c][1];
    }
    __syncthreads();
    {
        int bl = threadIdx.x;              // local b 0..127
        int pp  = bl >> 6;
        int sel = (bl >> 5) & 1;
        int ln  = bl & 31;
        const float* srf = (const float*)sr;
        float v[C_];
        #pragma unroll
        for (int c = 0; c < C_; c++) {
            float s = 0.f;
            #pragma unroll
            for (int ww = 0; ww < 4; ww++)
                s += srf[(((ww * 32 + ln) * C_ + c) * 2 + pp) * 2 + sel];
            v[c] = s;
        }
        float* o = part + ((size_t)ts * B_ + bbase + bl) * C_;
        #pragma unroll
        for (int c = 0; c < C_; c++) o[c] = v[c];
    }
}

// ---------------- kernel 5: sum the NSPLIT tree-split partials ----------------
__global__ __launch_bounds__(256)
void reduce_kernel(const float* __restrict__ part, float* __restrict__ out) {
    int i = blockIdx.x * blockDim.x + threadIdx.x;
    if (i >= B_ * C_) return;
    float s = 0.f;
    #pragma unroll
    for (int k = 0; k < NSPLIT; k++) s += part[(size_t)k * B_ * C_ + i];
    out[i] = s;
}

// ---------------- launcher ----------------
extern "C" void kernel_launch(void* const* d_in, const int* in_sizes, int n_in,
                              void* d_out, int out_size) {
    const float* x    = (const float*)d_in[0];
    const float* fm   = (const float*)d_in[1];
    const float* thr  = (const float*)d_in[2];
    const float* leaf = (const float*)d_in[3];
    const float* W1   = (const float*)d_in[4];
    const float* b1   = (const float*)d_in[5];
    const float* W2   = (const float*)d_in[6];
    const float* b2   = (const float*)d_in[7];
    float* out = (float*)d_out;

    float *gLP, *gAt, *gS, *gP;
    cudaGetSymbolAddress((void**)&gLP, g_LP);
    cudaGetSymbolAddress((void**)&gAt, g_attn);
    cudaGetSymbolAddress((void**)&gS,  g_s);
    cudaGetSymbolAddress((void**)&gP,  g_part);

    cudaFuncSetAttribute(attn_kernel, cudaFuncAttributeMaxDynamicSharedMemorySize,
                         ATTN_SMEM_FLOATS * 4);
    cudaFuncSetAttribute(kz_kernel,   cudaFuncAttributeMaxDynamicSharedMemorySize,
                         KZ_SMEM_FLOATS * 4);
    cudaFuncSetAttribute(kmix_kernel, cudaFuncAttributeMaxDynamicSharedMemorySize,
                         KMIX_SMEM_FLOATS * 4);
    (void)in_sizes; (void)n_in; (void)out_size;

    prep_leaf_kernel<<<(T_ * L_ + 255) / 256, 256>>>(leaf, gLP);
    attn_kernel<<<B_ / 16, 512, ATTN_SMEM_FLOATS * 4>>>(x, W1, b1, W2, b2, gAt);
    kz_kernel<<<dim3(B_ / 128, TD_ / 128), 256, KZ_SMEM_FLOATS * 4>>>(x, fm, thr, gS);
    kmix_kernel<<<dim3(B_ / 128, NSPLIT), 128, KMIX_SMEM_FLOATS * 4>>>(gS, gAt, gLP, gP);
    reduce_kernel<<<(B_ * C_ + 255) / 256, 256>>>(gP, out);
}

// round 8
// speedup vs baseline: 1.5500x; 1.0585x over previous
#include <cuda_runtime.h>
#include <math.h>

// Problem constants
#define B_  8192
#define T_  128
#define D_  7
#define I_  128
#define C_  10
#define L_  128
#define TD_ 896          // T_*D_
#define LPROW 24         // duplicated leafP row: 10 classes x {v,v} = 20, pad to 24
#define NSPLIT 64        // kmix tree splits (2 trees per block)

typedef unsigned long long u64x;

__device__ __forceinline__ u64x pk2(float lo, float hi) {
    u64x r; asm("mov.b64 %0, {%1, %2};" : "=l"(r) : "f"(lo), "f"(hi)); return r;
}
__device__ __forceinline__ void upk2(float& lo, float& hi, u64x v) {
    asm("mov.b64 {%0, %1}, %2;" : "=f"(lo), "=f"(hi) : "l"(v));
}
__device__ __forceinline__ u64x mul2_(u64x a, u64x b) {
    u64x d; asm("mul.rn.f32x2 %0, %1, %2;" : "=l"(d) : "l"(a), "l"(b)); return d;
}
__device__ __forceinline__ u64x fma2_(u64x a, u64x b, u64x c) {
    u64x d; asm("fma.rn.f32x2 %0, %1, %2, %3;" : "=l"(d) : "l"(a), "l"(b), "l"(c)); return d;
}
__device__ __forceinline__ u64x d2u(double v) { return (u64x)__double_as_longlong(v); }

// ---------------- scratch (__device__ globals; no allocation) ----------------
__device__ float g_LP[T_ * L_ * LPROW];            // softmaxed leaf probs, duplicated pairs
__device__ float g_attn[T_ * B_];                  // attention, TRANSPOSED [t][b]
__device__ float g_s[(size_t)TD_ * B_];            // softsign(z), TRANSPOSED [t*7+d][b]
__device__ float g_part[NSPLIT * C_ * B_];         // kmix partials, planar [ts][c][b]

// ---------------- kernel 1: leaf softmax -> duplicated pairs ----------------
__global__ __launch_bounds__(256)
void prep_leaf_kernel(const float* __restrict__ leaf, float* __restrict__ lp) {
    int idx = blockIdx.x * blockDim.x + threadIdx.x;   // t*128 + l
    if (idx >= T_ * L_) return;
    const float* in = leaf + (size_t)idx * C_;
    float v[C_];
    float m = -1e30f;
    #pragma unroll
    for (int c = 0; c < C_; c++) { v[c] = in[c]; m = fmaxf(m, v[c]); }
    float sum = 0.f;
    #pragma unroll
    for (int c = 0; c < C_; c++) { v[c] = expf(v[c] - m); sum += v[c]; }
    float inv = 1.0f / sum;
    float* o = lp + (size_t)idx * LPROW;
    #pragma unroll
    for (int c = 0; c < C_; c++) { float p = v[c] * inv; o[2*c] = p; o[2*c+1] = p; }
    o[20] = 0.f; o[21] = 0.f; o[22] = 0.f; o[23] = 0.f;
}

// ---------------- kernel 2: MLP attention, W1/W2 staged in smem -------------
__global__ __launch_bounds__(512)
void attn_kernel(const float* __restrict__ x,  const float* __restrict__ W1,
                 const float* __restrict__ b1, const float* __restrict__ W2,
                 const float* __restrict__ b2, float* __restrict__ attn_out) {
    extern __shared__ float sma[];
    float* sW1  = sma;                   // 8192
    float* sW2  = sma + 8192;            // 8192
    float* sx   = sma + 16384;           // [16][128]
    float* sh   = sma + 16384 + 2048;    // [16][64]
    float* sout = sma + 16384 + 3072;    // [128][17]
    int w = threadIdx.x >> 5, lane = threadIdx.x & 31;
    int b0 = blockIdx.x * 16;
    int b = b0 + w;

    for (int i = threadIdx.x; i < 2048; i += 512) {
        ((float4*)sW1)[i] = ((const float4*)W1)[i];
        ((float4*)sW2)[i] = ((const float4*)W2)[i];
    }
    #pragma unroll
    for (int k = 0; k < 4; k++)
        sx[w * 128 + lane + 32 * k] = x[(size_t)b * I_ + lane + 32 * k];
    __syncthreads();

    float h0 = b1[lane], h1 = b1[lane + 32];
    #pragma unroll 4
    for (int i = 0; i < I_; i++) {
        float xi = sx[w * 128 + i];
        h0 = fmaf(xi, sW1[i * 64 + lane],      h0);
        h1 = fmaf(xi, sW1[i * 64 + lane + 32], h1);
    }
    sh[w * 64 + lane]      = fmaxf(h0, 0.f);
    sh[w * 64 + lane + 32] = fmaxf(h1, 0.f);
    __syncwarp();

    float lg[4];
    #pragma unroll
    for (int k = 0; k < 4; k++) lg[k] = b2[lane + 32 * k];
    #pragma unroll 4
    for (int j = 0; j < 64; j++) {
        float hj = sh[w * 64 + j];
        #pragma unroll
        for (int k = 0; k < 4; k++)
            lg[k] = fmaf(hj, sW2[j * T_ + lane + 32 * k], lg[k]);
    }
    float m = fmaxf(fmaxf(lg[0], lg[1]), fmaxf(lg[2], lg[3]));
    #pragma unroll
    for (int o = 16; o; o >>= 1) m = fmaxf(m, __shfl_xor_sync(0xffffffffu, m, o));
    float sum = 0.f;
    #pragma unroll
    for (int k = 0; k < 4; k++) { lg[k] = expf(lg[k] - m); sum += lg[k]; }
    #pragma unroll
    for (int o = 16; o; o >>= 1) sum += __shfl_xor_sync(0xffffffffu, sum, o);
    float inv = 1.0f / sum;
    #pragma unroll
    for (int k = 0; k < 4; k++) sout[(lane + 32 * k) * 17 + w] = lg[k] * inv;
    __syncthreads();

    for (int i = threadIdx.x; i < 128 * 16; i += 512) {
        int t = i >> 4, j = i & 15;
        attn_out[(size_t)t * B_ + b0 + j] = sout[t * 17 + j];
    }
}
#define ATTN_SMEM_FLOATS (16384 + 3072 + 128 * 17)

// ---------------- kernel 3: z GEMM (packed f32x2) + softsign ----------------
#define KZ_SMEM_FLOATS (128 * 132)
__global__ __launch_bounds__(256)
void kz_kernel(const float* __restrict__ x, const float* __restrict__ fm,
               const float* __restrict__ thr, float* __restrict__ s_out) {
    extern __shared__ float smz[];
    float* Ad = smz;                  // [32][260]
    float* Bs = smz + 32 * 260;       // [32][132]
    int tid = threadIdx.x;
    int b0 = blockIdx.x * 128;
    int n0 = blockIdx.y * 128;
    int tm = tid >> 4, tn = tid & 15;

    u64x acc[8][4];
    #pragma unroll
    for (int i = 0; i < 8; i++)
        #pragma unroll
        for (int j = 0; j < 4; j++) acc[i][j] = 0;

    for (int kc = 0; kc < 4; kc++) {
        __syncthreads();
        for (int idx = tid; idx < 1024; idx += 256) {
            int m = idx >> 3, k4 = idx & 7;
            float4 xv = *(const float4*)&x[(size_t)(b0 + m) * I_ + kc * 32 + 4 * k4];
            *(u64x*)&Ad[(4 * k4 + 0) * 260 + 2 * m] = pk2(xv.x, xv.x);
            *(u64x*)&Ad[(4 * k4 + 1) * 260 + 2 * m] = pk2(xv.y, xv.y);
            *(u64x*)&Ad[(4 * k4 + 2) * 260 + 2 * m] = pk2(xv.z, xv.z);
            *(u64x*)&Ad[(4 * k4 + 3) * 260 + 2 * m] = pk2(xv.w, xv.w);
        }
        for (int idx = tid; idx < 1024; idx += 256) {
            int n = idx >> 3, k4 = idx & 7;
            float4 fv = *(const float4*)&fm[(size_t)(n0 + n) * I_ + kc * 32 + 4 * k4];
            Bs[(4 * k4 + 0) * 132 + n] = fv.x;
            Bs[(4 * k4 + 1) * 132 + n] = fv.y;
            Bs[(4 * k4 + 2) * 132 + n] = fv.z;
            Bs[(4 * k4 + 3) * 132 + n] = fv.w;
        }
        __syncthreads();

        #pragma unroll 4
        for (int k = 0; k < 32; k++) {
            const float* aP = Ad + k * 260 + tm * 16;
            const float* bP = Bs + k * 132 + tn * 8;
            double2 A0 = *(const double2*)(aP);
            double2 A1 = *(const double2*)(aP + 4);
            double2 A2 = *(const double2*)(aP + 8);
            double2 A3 = *(const double2*)(aP + 12);
            double2 B0 = *(const double2*)(bP);
            double2 B1 = *(const double2*)(bP + 4);
            u64x a[8] = { d2u(A0.x), d2u(A0.y), d2u(A1.x), d2u(A1.y),
                          d2u(A2.x), d2u(A2.y), d2u(A3.x), d2u(A3.y) };
            u64x bb[4] = { d2u(B0.x), d2u(B0.y), d2u(B1.x), d2u(B1.y) };
            #pragma unroll
            for (int i = 0; i < 8; i++)
                #pragma unroll
                for (int j = 0; j < 4; j++)
                    acc[i][j] = fma2_(a[i], bb[j], acc[i][j]);
        }
    }

    __syncthreads();
    float* stage = smz;               // [n=128][132]
    float thv[8];
    #pragma unroll
    for (int j = 0; j < 8; j++) thv[j] = thr[n0 + tn * 8 + j];
    #pragma unroll
    for (int i = 0; i < 8; i++) {
        int m = tm * 8 + i;
        #pragma unroll
        for (int j = 0; j < 4; j++) {
            float lo, hi; upk2(lo, hi, acc[i][j]);
            float z0 = lo - thv[2 * j], z1 = hi - thv[2 * j + 1];
            stage[(tn * 8 + 2 * j)     * 132 + m] =
                fmaf(0.5f, __fdividef(z0, 1.0f + fabsf(z0)), 0.5f);
            stage[(tn * 8 + 2 * j + 1) * 132 + m] =
                fmaf(0.5f, __fdividef(z1, 1.0f + fabsf(z1)), 0.5f);
        }
    }
    __syncthreads();
    int w = tid >> 5, lane = tid & 31;
    #pragma unroll
    for (int i = 0; i < 16; i++) {
        int n = w * 16 + i;
        float4 v = *(const float4*)&stage[n * 132 + lane * 4];
        *(float4*)&s_out[(size_t)(n0 + n) * B_ + b0 + lane * 4] = v;
    }
}

// ---------------- kernel 4: leaf mix, shared slab + software pipeline -------
// grid (B/512, NSPLIT). block 128 threads cover 512 b (4 per thread:
// +0,+128,+256,+384); all warps share one LP slab per tree; 2 trees per block.
#define KMIX_SMEM_FLOATS (2 * L_ * LPROW)     // double-buffered slab, 24KB
__global__ __launch_bounds__(128, 3)
void kmix_kernel(const float* __restrict__ s_in, const float* __restrict__ attn,
                 const float* __restrict__ lp, float* __restrict__ part) {
    extern __shared__ float smm[];
    int tid = threadIdx.x;
    int bbase = blockIdx.x * 512;
    int ts = blockIdx.y;
    int t0 = ts * 2;

    const u64x ONE2 = 0x3f8000003f800000ULL;
    const u64x NEG2 = 0xbf800000bf800000ULL;

    u64x acc[C_][2];
    #pragma unroll
    for (int c = 0; c < C_; c++) { acc[c][0] = 0; acc[c][1] = 0; }

    // stage slab for tree t0 into buffer 0
    {
        const float4* src = (const float4*)(lp + (size_t)t0 * (L_ * LPROW));
        float4* dst = (float4*)smm;
        #pragma unroll
        for (int k = 0; k < 6; k++) dst[tid + 128 * k] = src[tid + 128 * k];
    }
    __syncthreads();

    #pragma unroll
    for (int tt = 0; tt < 2; tt++) {
        int t = t0 + tt;
        // issue staging of next tree's slab early (overlaps with compute)
        if (tt == 0) {
            const float4* src = (const float4*)(lp + (size_t)(t0 + 1) * (L_ * LPROW));
            float4* dst = (float4*)(smm + L_ * LPROW);
            #pragma unroll
            for (int k = 0; k < 6; k++) dst[tid + 128 * k] = src[tid + 128 * k];
        }
        const float* slab = smm + tt * (L_ * LPROW);

        // packed s, (1-s): pair0 = (b, b+128), pair1 = (b+256, b+384)
        u64x sv0[D_], mv0[D_], sv1[D_], mv1[D_];
        const float* sp = s_in + (size_t)(t * D_) * B_ + bbase + tid;
        #pragma unroll
        for (int d = 0; d < D_; d++) {
            const float* q = sp + (size_t)d * B_;
            sv0[d] = pk2(q[0],   q[128]);
            sv1[d] = pk2(q[256], q[384]);
            mv0[d] = fma2_(sv0[d], NEG2, ONE2);
            mv1[d] = fma2_(sv1[d], NEG2, ONE2);
        }
        const float* ap = attn + (size_t)t * B_ + bbase + tid;
        u64x a0 = pk2(ap[0],   ap[128]);
        u64x a1 = pk2(ap[256], ap[384]);

        // pLow bits 0..2
        u64x pl0[8], pl1[8];
        pl0[0] = sv0[0]; pl0[1] = mv0[0];
        pl1[0] = sv1[0]; pl1[1] = mv1[0];
        pl0[2] = mul2_(pl0[0], mv0[1]); pl0[3] = mul2_(pl0[1], mv0[1]);
        pl1[2] = mul2_(pl1[0], mv1[1]); pl1[3] = mul2_(pl1[1], mv1[1]);
        pl0[0] = mul2_(pl0[0], sv0[1]); pl0[1] = mul2_(pl0[1], sv0[1]);
        pl1[0] = mul2_(pl1[0], sv1[1]); pl1[1] = mul2_(pl1[1], sv1[1]);
        pl0[4] = mul2_(pl0[0], mv0[2]); pl0[5] = mul2_(pl0[1], mv0[2]);
        pl0[6] = mul2_(pl0[2], mv0[2]); pl0[7] = mul2_(pl0[3], mv0[2]);
        pl1[4] = mul2_(pl1[0], mv1[2]); pl1[5] = mul2_(pl1[1], mv1[2]);
        pl1[6] = mul2_(pl1[2], mv1[2]); pl1[7] = mul2_(pl1[3], mv1[2]);
        pl0[0] = mul2_(pl0[0], sv0[2]); pl0[1] = mul2_(pl0[1], sv0[2]);
        pl0[2] = mul2_(pl0[2], sv0[2]); pl0[3] = mul2_(pl0[3], sv0[2]);
        pl1[0] = mul2_(pl1[0], sv1[2]); pl1[1] = mul2_(pl1[1], sv1[2]);
        pl1[2] = mul2_(pl1[2], sv1[2]); pl1[3] = mul2_(pl1[3], sv1[2]);

        // ph4 basis (bits 3,4; attn folded) and f basis (bits 5,6)
        u64x t00 = mul2_(a0, sv0[3]), t01 = mul2_(a0, mv0[3]);
        u64x t10 = mul2_(a1, sv1[3]), t11 = mul2_(a1, mv1[3]);
        u64x ph40[4], ph41[4], f0[4], f1[4];
        ph40[0] = mul2_(t00, sv0[4]); ph40[1] = mul2_(t01, sv0[4]);
        ph40[2] = mul2_(t00, mv0[4]); ph40[3] = mul2_(t01, mv0[4]);
        ph41[0] = mul2_(t10, sv1[4]); ph41[1] = mul2_(t11, sv1[4]);
        ph41[2] = mul2_(t10, mv1[4]); ph41[3] = mul2_(t11, mv1[4]);
        f0[0] = mul2_(sv0[5], sv0[6]); f0[1] = mul2_(mv0[5], sv0[6]);
        f0[2] = mul2_(sv0[5], mv0[6]); f0[3] = mul2_(mv0[5], mv0[6]);
        f1[0] = mul2_(sv1[5], sv1[6]); f1[1] = mul2_(mv1[5], sv1[6]);
        f1[2] = mul2_(sv1[5], mv1[6]); f1[3] = mul2_(mv1[5], mv1[6]);

        // software-pipelined leaf loop: double-buffered class vectors
        double2 buf[2][5];
        buf[0][0] = *(const double2*)(slab);
        buf[0][1] = *(const double2*)(slab + 4);
        buf[0][2] = *(const double2*)(slab + 8);
        buf[0][3] = *(const double2*)(slab + 12);
        buf[0][4] = *(const double2*)(slab + 16);
        #pragma unroll
        for (int m = 0; m < 16; m++) {
            u64x pm0 = mul2_(ph40[m & 3], f0[m >> 2]);
            u64x pm1 = mul2_(ph41[m & 3], f1[m >> 2]);
            #pragma unroll
            for (int j = 0; j < 8; j++) {
                int l = m * 8 + j;
                int p = l & 1, np = p ^ 1;
                const float* Ln = slab + ((l + 1) & 127) * LPROW;
                buf[np][0] = *(const double2*)(Ln);
                buf[np][1] = *(const double2*)(Ln + 4);
                buf[np][2] = *(const double2*)(Ln + 8);
                buf[np][3] = *(const double2*)(Ln + 12);
                buf[np][4] = *(const double2*)(Ln + 16);
                u64x q0 = mul2_(pl0[j], pm0);
                u64x q1 = mul2_(pl1[j], pm1);
                acc[0][0] = fma2_(q0, d2u(buf[p][0].x), acc[0][0]);
                acc[0][1] = fma2_(q1, d2u(buf[p][0].x), acc[0][1]);
                acc[1][0] = fma2_(q0, d2u(buf[p][0].y), acc[1][0]);
                acc[1][1] = fma2_(q1, d2u(buf[p][0].y), acc[1][1]);
                acc[2][0] = fma2_(q0, d2u(buf[p][1].x), acc[2][0]);
                acc[2][1] = fma2_(q1, d2u(buf[p][1].x), acc[2][1]);
                acc[3][0] = fma2_(q0, d2u(buf[p][1].y), acc[3][0]);
                acc[3][1] = fma2_(q1, d2u(buf[p][1].y), acc[3][1]);
                acc[4][0] = fma2_(q0, d2u(buf[p][2].x), acc[4][0]);
                acc[4][1] = fma2_(q1, d2u(buf[p][2].x), acc[4][1]);
                acc[5][0] = fma2_(q0, d2u(buf[p][2].y), acc[5][0]);
                acc[5][1] = fma2_(q1, d2u(buf[p][2].y), acc[5][1]);
                acc[6][0] = fma2_(q0, d2u(buf[p][3].x), acc[6][0]);
                acc[6][1] = fma2_(q1, d2u(buf[p][3].x), acc[6][1]);
                acc[7][0] = fma2_(q0, d2u(buf[p][3].y), acc[7][0]);
                acc[7][1] = fma2_(q1, d2u(buf[p][3].y), acc[7][1]);
                acc[8][0] = fma2_(q0, d2u(buf[p][4].x), acc[8][0]);
                acc[8][1] = fma2_(q1, d2u(buf[p][4].x), acc[8][1]);
                acc[9][0] = fma2_(q0, d2u(buf[p][4].y), acc[9][0]);
                acc[9][1] = fma2_(q1, d2u(buf[p][4].y), acc[9][1]);
            }
        }
        __syncthreads();   // slab[tt+1] staged; also keeps buffers coherent
    }

    // planar partial store: part[ts][c][b], fully coalesced
    #pragma unroll
    for (int c = 0; c < C_; c++) {
        float v0, v1, v2, v3;
        upk2(v0, v1, acc[c][0]);
        upk2(v2, v3, acc[c][1]);
        float* o = part + ((size_t)ts * C_ + c) * B_ + bbase + tid;
        o[0]   = v0;
        o[128] = v1;
        o[256] = v2;
        o[384] = v3;
    }
}

// ---------------- kernel 5: sum the NSPLIT planar partials ----------------
__global__ __launch_bounds__(256)
void reduce_kernel(const float* __restrict__ part, float* __restrict__ out) {
    int idx = blockIdx.x * blockDim.x + threadIdx.x;    // c*B + b
    if (idx >= B_ * C_) return;
    int c = idx >> 13;           // / B_
    int b = idx & (B_ - 1);
    float s = 0.f;
    #pragma unroll
    for (int k = 0; k < NSPLIT; k++)
        s += part[((size_t)k * C_ + c) * B_ + b];
    out[(size_t)b * C_ + c] = s;
}

// ---------------- launcher ----------------
extern "C" void kernel_launch(void* const* d_in, const int* in_sizes, int n_in,
                              void* d_out, int out_size) {
    const float* x    = (const float*)d_in[0];
    const float* fm   = (const float*)d_in[1];
    const float* thr  = (const float*)d_in[2];
    const float* leaf = (const float*)d_in[3];
    const float* W1   = (const float*)d_in[4];
    const float* b1   = (const float*)d_in[5];
    const float* W2   = (const float*)d_in[6];
    const float* b2   = (const float*)d_in[7];
    float* out = (float*)d_out;

    float *gLP, *gAt, *gS, *gP;
    cudaGetSymbolAddress((void**)&gLP, g_LP);
    cudaGetSymbolAddress((void**)&gAt, g_attn);
    cudaGetSymbolAddress((void**)&gS,  g_s);
    cudaGetSymbolAddress((void**)&gP,  g_part);

    cudaFuncSetAttribute(attn_kernel, cudaFuncAttributeMaxDynamicSharedMemorySize,
                         ATTN_SMEM_FLOATS * 4);
    cudaFuncSetAttribute(kz_kernel,   cudaFuncAttributeMaxDynamicSharedMemorySize,
                         KZ_SMEM_FLOATS * 4);
    cudaFuncSetAttribute(kmix_kernel, cudaFuncAttributeMaxDynamicSharedMemorySize,
                         KMIX_SMEM_FLOATS * 4);
    (void)in_sizes; (void)n_in; (void)out_size;

    prep_leaf_kernel<<<(T_ * L_ + 255) / 256, 256>>>(leaf, gLP);
    attn_kernel<<<B_ / 16, 512, ATTN_SMEM_FLOATS * 4>>>(x, W1, b1, W2, b2, gAt);
    kz_kernel<<<dim3(B_ / 128, TD_ / 128), 256, KZ_SMEM_FLOATS * 4>>>(x, fm, thr, gS);
    kmix_kernel<<<dim3(B_ / 512, NSPLIT), 128, KMIX_SMEM_FLOATS * 4>>>(gS, gAt, gLP, gP);
    reduce_kernel<<<(B_ * C_ + 255) / 256, 256>>>(gP, out);
}

// round 13
// speedup vs baseline: 1.6106x; 1.0392x over previous
#include <cuda_runtime.h>
#include <stdint.h>
#include <math.h>

// Problem constants
#define B_  8192
#define T_  128
#define D_  7
#define I_  128
#define C_  10
#define L_  128
#define TD_ 896          // T_*D_
#define LPROW 24         // duplicated leafP row: 10 classes x {v,v} = 20, pad to 24
#define NSPLIT 64        // kmix tree splits (2 trees per block)
#define NZC 28           // complement-index capacity (actual = 26)

typedef unsigned long long u64x;

__device__ __forceinline__ u64x pk2(float lo, float hi) {
    u64x r; asm("mov.b64 %0, {%1, %2};" : "=l"(r) : "f"(lo), "f"(hi)); return r;
}
__device__ __forceinline__ void upk2(float& lo, float& hi, u64x v) {
    asm("mov.b64 {%0, %1}, %2;" : "=f"(lo), "=f"(hi) : "l"(v));
}
__device__ __forceinline__ u64x mul2_(u64x a, u64x b) {
    u64x d; asm("mul.rn.f32x2 %0, %1, %2;" : "=l"(d) : "l"(a), "l"(b)); return d;
}
__device__ __forceinline__ u64x fma2_(u64x a, u64x b, u64x c) {
    u64x d; asm("fma.rn.f32x2 %0, %1, %2, %3;" : "=l"(d) : "l"(a), "l"(b), "l"(c)); return d;
}
__device__ __forceinline__ u64x d2u(double v) { return (u64x)__double_as_longlong(v); }

// ---------------- scratch (__device__ globals; no allocation) ----------------
__device__ float g_LP[T_ * L_ * LPROW];            // softmaxed leaf probs, duplicated pairs
__device__ float g_attn[T_ * B_];                  // attention, TRANSPOSED [t][b]
__device__ float g_s[(size_t)TD_ * B_];            // softsign(z), TRANSPOSED [t*7+d][b]
__device__ float g_part[NSPLIT * C_ * B_];         // kmix partials, planar [ts][c][b]
__device__ float g_xT[(size_t)I_ * B_];            // x transposed [i][b]
__device__ int   g_cidx[TD_ * NZC];                // complement (zero-mask) indices

// ---------------- kernel 1: leaf softmax -> duplicated pairs ----------------
__global__ __launch_bounds__(256)
void prep_leaf_kernel(const float* __restrict__ leaf, float* __restrict__ lp) {
    int idx = blockIdx.x * blockDim.x + threadIdx.x;   // t*128 + l
    if (idx >= T_ * L_) return;
    const float* in = leaf + (size_t)idx * C_;
    float v[C_];
    float m = -1e30f;
    #pragma unroll
    for (int c = 0; c < C_; c++) { v[c] = in[c]; m = fmaxf(m, v[c]); }
    float sum = 0.f;
    #pragma unroll
    for (int c = 0; c < C_; c++) { v[c] = expf(v[c] - m); sum += v[c]; }
    float inv = 1.0f / sum;
    float* o = lp + (size_t)idx * LPROW;
    #pragma unroll
    for (int c = 0; c < C_; c++) { float p = v[c] * inv; o[2*c] = p; o[2*c+1] = p; }
    o[20] = 0.f; o[21] = 0.f; o[22] = 0.f; o[23] = 0.f;
}

// ---------------- kernel 1b: complement index lists ----------------
__global__ __launch_bounds__(128)
void prep_cidx_kernel(const float* __restrict__ fm, int* __restrict__ cidx) {
    int n = blockIdx.x * blockDim.x + threadIdx.x;
    if (n >= TD_) return;
    int cnt = 0;
    for (int i = 0; i < I_; i++) {
        if (fm[(size_t)n * I_ + i] < 0.5f && cnt < NZC) cidx[n * NZC + cnt++] = i;
    }
    while (cnt < NZC) cidx[n * NZC + cnt++] = I_;   // sentinel -> zero row
}

// ---------------- kernel 1c: transpose x -> xT[i][b] ----------------
__global__ __launch_bounds__(256)
void xpose_kernel(const float* __restrict__ x, float* __restrict__ xT) {
    __shared__ float t[32][33];
    int bx = blockIdx.x * 32, ix = blockIdx.y * 32;
    int l = threadIdx.x & 31, w = threadIdx.x >> 5;
    #pragma unroll
    for (int r = 0; r < 32; r += 8)
        t[w + r][l] = x[(size_t)(bx + w + r) * I_ + ix + l];
    __syncthreads();
    #pragma unroll
    for (int r = 0; r < 32; r += 8)
        xT[(size_t)(ix + w + r) * B_ + bx + l] = t[l][w + r];
}

// ---------------- kernel 2: MLP attention, W1/W2 staged in smem -------------
__global__ __launch_bounds__(512)
void attn_kernel(const float* __restrict__ x,  const float* __restrict__ W1,
                 const float* __restrict__ b1, const float* __restrict__ W2,
                 const float* __restrict__ b2, float* __restrict__ attn_out) {
    extern __shared__ float sma[];
    float* sW1  = sma;                   // 8192
    float* sW2  = sma + 8192;            // 8192
    float* sx   = sma + 16384;           // [16][128]
    float* sh   = sma + 16384 + 2048;    // [16][64]
    float* sout = sma + 16384 + 3072;    // [128][17]
    int w = threadIdx.x >> 5, lane = threadIdx.x & 31;
    int b0 = blockIdx.x * 16;
    int b = b0 + w;

    for (int i = threadIdx.x; i < 2048; i += 512) {
        ((float4*)sW1)[i] = ((const float4*)W1)[i];
        ((float4*)sW2)[i] = ((const float4*)W2)[i];
    }
    #pragma unroll
    for (int k = 0; k < 4; k++)
        sx[w * 128 + lane + 32 * k] = x[(size_t)b * I_ + lane + 32 * k];
    __syncthreads();

    float h0 = b1[lane], h1 = b1[lane + 32];
    #pragma unroll 4
    for (int i = 0; i < I_; i++) {
        float xi = sx[w * 128 + i];
        h0 = fmaf(xi, sW1[i * 64 + lane],      h0);
        h1 = fmaf(xi, sW1[i * 64 + lane + 32], h1);
    }
    sh[w * 64 + lane]      = fmaxf(h0, 0.f);
    sh[w * 64 + lane + 32] = fmaxf(h1, 0.f);
    __syncwarp();

    float lg[4];
    #pragma unroll
    for (int k = 0; k < 4; k++) lg[k] = b2[lane + 32 * k];
    #pragma unroll 4
    for (int j = 0; j < 64; j++) {
        float hj = sh[w * 64 + j];
        #pragma unroll
        for (int k = 0; k < 4; k++)
            lg[k] = fmaf(hj, sW2[j * T_ + lane + 32 * k], lg[k]);
    }
    float m = fmaxf(fmaxf(lg[0], lg[1]), fmaxf(lg[2], lg[3]));
    #pragma unroll
    for (int o = 16; o; o >>= 1) m = fmaxf(m, __shfl_xor_sync(0xffffffffu, m, o));
    float sum = 0.f;
    #pragma unroll
    for (int k = 0; k < 4; k++) { lg[k] = expf(lg[k] - m); sum += lg[k]; }
    #pragma unroll
    for (int o = 16; o; o >>= 1) sum += __shfl_xor_sync(0xffffffffu, sum, o);
    float inv = 1.0f / sum;
    #pragma unroll
    for (int k = 0; k < 4; k++) sout[(lane + 32 * k) * 17 + w] = lg[k] * inv;
    __syncthreads();

    for (int i = threadIdx.x; i < 128 * 16; i += 512) {
        int t = i >> 4, j = i & 15;
        attn_out[(size_t)t * B_ + b0 + j] = sout[t * 17 + j];
    }
}
#define ATTN_SMEM_FLOATS (16384 + 3072 + 128 * 17)

// ---------------- kernel 3: z via complement sparsity + softsign ------------
// z[n][b] = rowsum(x)[b] - sum_{j in zero-set(n)} x[b][idx] ; exactly 26 terms.
// tile: 128 b x 128 n. smem xs[129][132] ([i][b], row 128 = zeros), rs[128].
#define KZS_SMEM_BYTES ((129 * 132 + 128) * 4)
__global__ __launch_bounds__(128)
void kz_sparse_kernel(const float* __restrict__ xT, const int* __restrict__ cidx,
                      const float* __restrict__ thr, float* __restrict__ s_out) {
    extern __shared__ float sms[];
    float* xs = sms;                 // [129][132]
    float* rs = sms + 129 * 132;     // [128]
    int tid = threadIdx.x, w = tid >> 5, lane = tid & 31;
    int b0 = blockIdx.x * 128, n0 = blockIdx.y * 128;

    // stage xT tile (coalesced reads, conflict-free STS.128)
    for (int it = tid; it < 128 * 32; it += 128) {
        int i = it >> 5, c = it & 31;
        float4 v = *(const float4*)&xT[(size_t)i * B_ + b0 + c * 4];
        *(float4*)&xs[i * 132 + c * 4] = v;
    }
    xs[128 * 132 + tid] = 0.f;       // sentinel zero row (tid 0..127)
    __syncthreads();

    // rowsum per b (tid = local b)
    {
        float s0 = 0.f, s1 = 0.f, s2 = 0.f, s3 = 0.f;
        for (int i = 0; i < I_; i += 4) {
            s0 += xs[(i + 0) * 132 + tid];
            s1 += xs[(i + 1) * 132 + tid];
            s2 += xs[(i + 2) * 132 + tid];
            s3 += xs[(i + 3) * 132 + tid];
        }
        rs[tid] = (s0 + s1) + (s2 + s3);
    }
    __syncthreads();

    const u64x NEG2 = 0xbf800000bf800000ULL;
    const u64x ONE2 = 0x3f8000003f800000ULL;

    // warp w handles n = n0 + w*32 + q ; lane covers b = b0 + lane*4 .. +3
    for (int q = 0; q < 32; q++) {
        int n = n0 + w * 32 + q;
        const int* ci = cidx + n * NZC;
        double2 r2 = *(const double2*)&rs[lane * 4];
        // two interleaved chains per pair to shorten the dependency chain
        u64x aE01 = d2u(r2.x), aO01 = 0;     // aO starts at +0, accumulates -x
        u64x aE23 = d2u(r2.y), aO23 = 0;
        #pragma unroll
        for (int j = 0; j < NZC; j += 2) {
            int i0 = __ldg(ci + j);
            int i1 = __ldg(ci + j + 1);
            double2 x0 = *(const double2*)&xs[i0 * 132 + lane * 4];
            double2 x1 = *(const double2*)&xs[i1 * 132 + lane * 4];
            aE01 = fma2_(d2u(x0.x), NEG2, aE01);
            aE23 = fma2_(d2u(x0.y), NEG2, aE23);
            aO01 = fma2_(d2u(x1.x), NEG2, aO01);
            aO23 = fma2_(d2u(x1.y), NEG2, aO23);
        }
        u64x a01 = fma2_(aO01, ONE2, aE01);
        u64x a23 = fma2_(aO23, ONE2, aE23);

        float th = __ldg(&thr[n]);
        float z0, z1, z2, z3;
        upk2(z0, z1, a01); upk2(z2, z3, a23);
        z0 -= th; z1 -= th; z2 -= th; z3 -= th;
        float4 o;
        o.x = fmaf(0.5f, __fdividef(z0, 1.0f + fabsf(z0)), 0.5f);
        o.y = fmaf(0.5f, __fdividef(z1, 1.0f + fabsf(z1)), 0.5f);
        o.z = fmaf(0.5f, __fdividef(z2, 1.0f + fabsf(z2)), 0.5f);
        o.w = fmaf(0.5f, __fdividef(z3, 1.0f + fabsf(z3)), 0.5f);
        *(float4*)&s_out[(size_t)n * B_ + b0 + lane * 4] = o;
    }
}

// ---------------- kernel 4: leaf mix, shared slab + software pipeline -------
#define KMIX_SMEM_FLOATS (2 * L_ * LPROW)     // double-buffered slab, 24KB
__global__ __launch_bounds__(128, 3)
void kmix_kernel(const float* __restrict__ s_in, const float* __restrict__ attn,
                 const float* __restrict__ lp, float* __restrict__ part) {
    extern __shared__ float smm[];
    int tid = threadIdx.x;
    int bbase = blockIdx.x * 512;
    int ts = blockIdx.y;
    int t0 = ts * 2;

    const u64x ONE2 = 0x3f8000003f800000ULL;
    const u64x NEG2 = 0xbf800000bf800000ULL;

    u64x acc[C_][2];
    #pragma unroll
    for (int c = 0; c < C_; c++) { acc[c][0] = 0; acc[c][1] = 0; }

    {
        const float4* src = (const float4*)(lp + (size_t)t0 * (L_ * LPROW));
        float4* dst = (float4*)smm;
        #pragma unroll
        for (int k = 0; k < 6; k++) dst[tid + 128 * k] = src[tid + 128 * k];
    }
    __syncthreads();

    #pragma unroll
    for (int tt = 0; tt < 2; tt++) {
        int t = t0 + tt;
        if (tt == 0) {
            const float4* src = (const float4*)(lp + (size_t)(t0 + 1) * (L_ * LPROW));
            float4* dst = (float4*)(smm + L_ * LPROW);
            #pragma unroll
            for (int k = 0; k < 6; k++) dst[tid + 128 * k] = src[tid + 128 * k];
        }
        const float* slab = smm + tt * (L_ * LPROW);

        u64x sv0[D_], mv0[D_], sv1[D_], mv1[D_];
        const float* sp = s_in + (size_t)(t * D_) * B_ + bbase + tid;
        #pragma unroll
        for (int d = 0; d < D_; d++) {
            const float* q = sp + (size_t)d * B_;
            sv0[d] = pk2(q[0],   q[128]);
            sv1[d] = pk2(q[256], q[384]);
            mv0[d] = fma2_(sv0[d], NEG2, ONE2);
            mv1[d] = fma2_(sv1[d], NEG2, ONE2);
        }
        const float* ap = attn + (size_t)t * B_ + bbase + tid;
        u64x a0 = pk2(ap[0],   ap[128]);
        u64x a1 = pk2(ap[256], ap[384]);

        u64x pl0[8], pl1[8];
        pl0[0] = sv0[0]; pl0[1] = mv0[0];
        pl1[0] = sv1[0]; pl1[1] = mv1[0];
        pl0[2] = mul2_(pl0[0], mv0[1]); pl0[3] = mul2_(pl0[1], mv0[1]);
        pl1[2] = mul2_(pl1[0], mv1[1]); pl1[3] = mul2_(pl1[1], mv1[1]);
        pl0[0] = mul2_(pl0[0], sv0[1]); pl0[1] = mul2_(pl0[1], sv0[1]);
        pl1[0] = mul2_(pl1[0], sv1[1]); pl1[1] = mul2_(pl1[1], sv1[1]);
        pl0[4] = mul2_(pl0[0], mv0[2]); pl0[5] = mul2_(pl0[1], mv0[2]);
        pl0[6] = mul2_(pl0[2], mv0[2]); pl0[7] = mul2_(pl0[3], mv0[2]);
        pl1[4] = mul2_(pl1[0], mv1[2]); pl1[5] = mul2_(pl1[1], mv1[2]);
        pl1[6] = mul2_(pl1[2], mv1[2]); pl1[7] = mul2_(pl1[3], mv1[2]);
        pl0[0] = mul2_(pl0[0], sv0[2]); pl0[1] = mul2_(pl0[1], sv0[2]);
        pl0[2] = mul2_(pl0[2], sv0[2]); pl0[3] = mul2_(pl0[3], sv0[2]);
        pl1[0] = mul2_(pl1[0], sv1[2]); pl1[1] = mul2_(pl1[1], sv1[2]);
        pl1[2] = mul2_(pl1[2], sv1[2]); pl1[3] = mul2_(pl1[3], sv1[2]);

        u64x t00 = mul2_(a0, sv0[3]), t01 = mul2_(a0, mv0[3]);
        u64x t10 = mul2_(a1, sv1[3]), t11 = mul2_(a1, mv1[3]);
        u64x ph40[4], ph41[4], f0[4], f1[4];
        ph40[0] = mul2_(t00, sv0[4]); ph40[1] = mul2_(t01, sv0[4]);
        ph40[2] = mul2_(t00, mv0[4]); ph40[3] = mul2_(t01, mv0[4]);
        ph41[0] = mul2_(t10, sv1[4]); ph41[1] = mul2_(t11, sv1[4]);
        ph41[2] = mul2_(t10, mv1[4]); ph41[3] = mul2_(t11, mv1[4]);
        f0[0] = mul2_(sv0[5], sv0[6]); f0[1] = mul2_(mv0[5], sv0[6]);
        f0[2] = mul2_(sv0[5], mv0[6]); f0[3] = mul2_(mv0[5], mv0[6]);
        f1[0] = mul2_(sv1[5], sv1[6]); f1[1] = mul2_(mv1[5], sv1[6]);
        f1[2] = mul2_(sv1[5], mv1[6]); f1[3] = mul2_(mv1[5], mv1[6]);

        double2 buf[2][5];
        buf[0][0] = *(const double2*)(slab);
        buf[0][1] = *(const double2*)(slab + 4);
        buf[0][2] = *(const double2*)(slab + 8);
        buf[0][3] = *(const double2*)(slab + 12);
        buf[0][4] = *(const double2*)(slab + 16);
        #pragma unroll
        for (int m = 0; m < 16; m++) {
            u64x pm0 = mul2_(ph40[m & 3], f0[m >> 2]);
            u64x pm1 = mul2_(ph41[m & 3], f1[m >> 2]);
            #pragma unroll
            for (int j = 0; j < 8; j++) {
                int l = m * 8 + j;
                int p = l & 1, np = p ^ 1;
                const float* Ln = slab + ((l + 1) & 127) * LPROW;
                buf[np][0] = *(const double2*)(Ln);
                buf[np][1] = *(const double2*)(Ln + 4);
                buf[np][2] = *(const double2*)(Ln + 8);
                buf[np][3] = *(const double2*)(Ln + 12);
                buf[np][4] = *(const double2*)(Ln + 16);
                u64x q0 = mul2_(pl0[j], pm0);
                u64x q1 = mul2_(pl1[j], pm1);
                acc[0][0] = fma2_(q0, d2u(buf[p][0].x), acc[0][0]);
                acc[0][1] = fma2_(q1, d2u(buf[p][0].x), acc[0][1]);
                acc[1][0] = fma2_(q0, d2u(buf[p][0].y), acc[1][0]);
                acc[1][1] = fma2_(q1, d2u(buf[p][0].y), acc[1][1]);
                acc[2][0] = fma2_(q0, d2u(buf[p][1].x), acc[2][0]);
                acc[2][1] = fma2_(q1, d2u(buf[p][1].x), acc[2][1]);
                acc[3][0] = fma2_(q0, d2u(buf[p][1].y), acc[3][0]);
                acc[3][1] = fma2_(q1, d2u(buf[p][1].y), acc[3][1]);
                acc[4][0] = fma2_(q0, d2u(buf[p][2].x), acc[4][0]);
                acc[4][1] = fma2_(q1, d2u(buf[p][2].x), acc[4][1]);
                acc[5][0] = fma2_(q0, d2u(buf[p][2].y), acc[5][0]);
                acc[5][1] = fma2_(q1, d2u(buf[p][2].y), acc[5][1]);
                acc[6][0] = fma2_(q0, d2u(buf[p][3].x), acc[6][0]);
                acc[6][1] = fma2_(q1, d2u(buf[p][3].x), acc[6][1]);
                acc[7][0] = fma2_(q0, d2u(buf[p][3].y), acc[7][0]);
                acc[7][1] = fma2_(q1, d2u(buf[p][3].y), acc[7][1]);
                acc[8][0] = fma2_(q0, d2u(buf[p][4].x), acc[8][0]);
                acc[8][1] = fma2_(q1, d2u(buf[p][4].x), acc[8][1]);
                acc[9][0] = fma2_(q0, d2u(buf[p][4].y), acc[9][0]);
                acc[9][1] = fma2_(q1, d2u(buf[p][4].y), acc[9][1]);
            }
        }
        __syncthreads();
    }

    #pragma unroll
    for (int c = 0; c < C_; c++) {
        float v0, v1, v2, v3;
        upk2(v0, v1, acc[c][0]);
        upk2(v2, v3, acc[c][1]);
        float* o = part + ((size_t)ts * C_ + c) * B_ + bbase + tid;
        o[0]   = v0;
        o[128] = v1;
        o[256] = v2;
        o[384] = v3;
    }
}

// ---------------- kernel 5: sum the NSPLIT planar partials ----------------
__global__ __launch_bounds__(256)
void reduce_kernel(const float* __restrict__ part, float* __restrict__ out) {
    int idx = blockIdx.x * blockDim.x + threadIdx.x;    // c*B + b
    if (idx >= B_ * C_) return;
    int c = idx >> 13;           // / B_
    int b = idx & (B_ - 1);
    float s = 0.f;
    #pragma unroll
    for (int k = 0; k < NSPLIT; k++)
        s += part[((size_t)k * C_ + c) * B_ + b];
    out[(size_t)b * C_ + c] = s;
}

// ---------------- launcher ----------------
extern "C" void kernel_launch(void* const* d_in, const int* in_sizes, int n_in,
                              void* d_out, int out_size) {
    const float* x    = (const float*)d_in[0];
    const float* fm   = (const float*)d_in[1];
    const float* thr  = (const float*)d_in[2];
    const float* leaf = (const float*)d_in[3];
    const float* W1   = (const float*)d_in[4];
    const float* b1   = (const float*)d_in[5];
    const float* W2   = (const float*)d_in[6];
    const float* b2   = (const float*)d_in[7];
    float* out = (float*)d_out;

    float *gLP, *gAt, *gS, *gP, *gXT;
    int* gCI;
    cudaGetSymbolAddress((void**)&gLP, g_LP);
    cudaGetSymbolAddress((void**)&gAt, g_attn);
    cudaGetSymbolAddress((void**)&gS,  g_s);
    cudaGetSymbolAddress((void**)&gP,  g_part);
    cudaGetSymbolAddress((void**)&gXT, g_xT);
    cudaGetSymbolAddress((void**)&gCI, g_cidx);

    cudaFuncSetAttribute(attn_kernel, cudaFuncAttributeMaxDynamicSharedMemorySize,
                         ATTN_SMEM_FLOATS * 4);
    cudaFuncSetAttribute(kz_sparse_kernel, cudaFuncAttributeMaxDynamicSharedMemorySize,
                         KZS_SMEM_BYTES);
    cudaFuncSetAttribute(kmix_kernel, cudaFuncAttributeMaxDynamicSharedMemorySize,
                         KMIX_SMEM_FLOATS * 4);
    (void)in_sizes; (void)n_in; (void)out_size;

    prep_leaf_kernel<<<(T_ * L_ + 255) / 256, 256>>>(leaf, gLP);
    prep_cidx_kernel<<<(TD_ + 127) / 128, 128>>>(fm, gCI);
    xpose_kernel<<<dim3(B_ / 32, I_ / 32), 256>>>(x, gXT);
    attn_kernel<<<B_ / 16, 512, ATTN_SMEM_FLOATS * 4>>>(x, W1, b1, W2, b2, gAt);
    kz_sparse_kernel<<<dim3(B_ / 128, TD_ / 128), 128, KZS_SMEM_BYTES>>>(gXT, gCI, thr, gS);
    kmix_kernel<<<dim3(B_ / 512, NSPLIT), 128, KMIX_SMEM_FLOATS * 4>>>(gS, gAt, gLP, gP);
    reduce_kernel<<<(B_ * C_ + 255) / 256, 256>>>(gP, out);
}

// round 14
// speedup vs baseline: 1.7460x; 1.0840x over previous
#include <cuda_runtime.h>
#include <stdint.h>
#include <math.h>

// Problem constants
#define B_  8192
#define T_  128
#define D_  7
#define I_  128
#define C_  10
#define L_  128
#define TD_ 896          // T_*D_
#define LPROW 24         // duplicated leafP row: 10 classes x {v,v} = 20, pad to 24
#define NSPLIT 64        // kmix tree splits (2 trees per block)
#define NZC 28           // complement-index capacity (actual = 26)

typedef unsigned long long u64x;

__device__ __forceinline__ u64x pk2(float lo, float hi) {
    u64x r; asm("mov.b64 %0, {%1, %2};" : "=l"(r) : "f"(lo), "f"(hi)); return r;
}
__device__ __forceinline__ void upk2(float& lo, float& hi, u64x v) {
    asm("mov.b64 {%0, %1}, %2;" : "=f"(lo), "=f"(hi) : "l"(v));
}
__device__ __forceinline__ u64x mul2_(u64x a, u64x b) {
    u64x d; asm("mul.rn.f32x2 %0, %1, %2;" : "=l"(d) : "l"(a), "l"(b)); return d;
}
__device__ __forceinline__ u64x fma2_(u64x a, u64x b, u64x c) {
    u64x d; asm("fma.rn.f32x2 %0, %1, %2, %3;" : "=l"(d) : "l"(a), "l"(b), "l"(c)); return d;
}
__device__ __forceinline__ u64x d2u(double v) { return (u64x)__double_as_longlong(v); }

// ---------------- scratch (__device__ globals; no allocation) ----------------
__device__ float g_LP[T_ * L_ * LPROW];            // softmaxed leaf probs, duplicated pairs
__device__ float g_attn[T_ * B_];                  // attention, TRANSPOSED [t][b]
__device__ float g_s[(size_t)TD_ * B_];            // softsign(z), TRANSPOSED [t*7+d][b]
__device__ float g_part[NSPLIT * C_ * B_];         // kmix partials, planar [ts][c][b]
__device__ float g_xT[(size_t)I_ * B_];            // x transposed [i][b]
__device__ int   g_cidx[TD_ * NZC];                // complement (zero-mask) indices

// ---------------- kernel 1: leaf softmax -> duplicated pairs ----------------
__global__ __launch_bounds__(256)
void prep_leaf_kernel(const float* __restrict__ leaf, float* __restrict__ lp) {
    int idx = blockIdx.x * blockDim.x + threadIdx.x;   // t*128 + l
    if (idx >= T_ * L_) return;
    const float* in = leaf + (size_t)idx * C_;
    float v[C_];
    float m = -1e30f;
    #pragma unroll
    for (int c = 0; c < C_; c++) { v[c] = in[c]; m = fmaxf(m, v[c]); }
    float sum = 0.f;
    #pragma unroll
    for (int c = 0; c < C_; c++) { v[c] = expf(v[c] - m); sum += v[c]; }
    float inv = 1.0f / sum;
    float* o = lp + (size_t)idx * LPROW;
    #pragma unroll
    for (int c = 0; c < C_; c++) { float p = v[c] * inv; o[2*c] = p; o[2*c+1] = p; }
    o[20] = 0.f; o[21] = 0.f; o[22] = 0.f; o[23] = 0.f;
}

// ---------------- kernel 1b: complement index lists ----------------
__global__ __launch_bounds__(128)
void prep_cidx_kernel(const float* __restrict__ fm, int* __restrict__ cidx) {
    int n = blockIdx.x * blockDim.x + threadIdx.x;
    if (n >= TD_) return;
    int cnt = 0;
    for (int i = 0; i < I_; i++) {
        if (fm[(size_t)n * I_ + i] < 0.5f && cnt < NZC) cidx[n * NZC + cnt++] = i;
    }
    while (cnt < NZC) cidx[n * NZC + cnt++] = I_;   // sentinel -> zero row
}

// ---------------- kernel 1c: transpose x -> xT[i][b] ----------------
__global__ __launch_bounds__(256)
void xpose_kernel(const float* __restrict__ x, float* __restrict__ xT) {
    __shared__ float t[32][33];
    int bx = blockIdx.x * 32, ix = blockIdx.y * 32;
    int l = threadIdx.x & 31, w = threadIdx.x >> 5;
    #pragma unroll
    for (int r = 0; r < 32; r += 8)
        t[w + r][l] = x[(size_t)(bx + w + r) * I_ + ix + l];
    __syncthreads();
    #pragma unroll
    for (int r = 0; r < 32; r += 8)
        xT[(size_t)(ix + w + r) * B_ + bx + l] = t[l][w + r];
}

// ---------------- kernel 2: MLP attention, register-tiled two-phase GEMM ----
// block: 64 b-rows, 256 threads.
// phase1: [64b x 64h x 128k], micro 4x4 -> relu -> As2[h][m]
// phase2: [64b x 128t x 64k], micro 4x8 -> +b2 -> softmax(rows via 16-lane shfl)
// smem aliasing: bufA = As1 then Bs2; bufB = Bs1 then As2; sout separate.
#define A1S 68
#define B1S 68
#define A2S 68
#define B2S 132
#define SOS 66
#define ATTN_SMEM_FLOATS (8704 + 8704 + 8448)
__global__ __launch_bounds__(256, 2)
void attn_kernel(const float* __restrict__ x,  const float* __restrict__ W1,
                 const float* __restrict__ b1, const float* __restrict__ W2,
                 const float* __restrict__ b2, float* __restrict__ attn_out) {
    extern __shared__ float sma[];
    float* bufA = sma;                 // 8704: As1 [k=128][m=64] s68 ; later Bs2 [k=64][t=128] s132
    float* bufB = sma + 8704;          // 8704: Bs1 [k=128][h=64] s68 ; later As2 [h=64][m=64] s68
    float* sout = sma + 17408;         // 8448: [t=128][m=64] s66
    int tid = threadIdx.x;
    int b0 = blockIdx.x * 64;
    int tm = tid >> 4, tn = tid & 15;

    // stage As1 (x tile, k-major) and Bs1 (W1, k-major)
    for (int idx = tid; idx < 2048; idx += 256) {
        int m = idx >> 5, k4 = idx & 31;
        float4 v = *(const float4*)&x[(size_t)(b0 + m) * I_ + 4 * k4];
        bufA[(4 * k4 + 0) * A1S + m] = v.x;
        bufA[(4 * k4 + 1) * A1S + m] = v.y;
        bufA[(4 * k4 + 2) * A1S + m] = v.z;
        bufA[(4 * k4 + 3) * A1S + m] = v.w;
    }
    for (int idx = tid; idx < 2048; idx += 256) {
        int i = idx >> 4, h4 = idx & 15;
        float4 v = *(const float4*)&W1[(size_t)i * 64 + 4 * h4];
        *(float4*)&bufB[i * B1S + 4 * h4] = v;
    }
    __syncthreads();

    // phase 1 GEMM: acc[4m][4h]
    float acc[4][4];
    {
        float bb1 = 0.f;   // init from b1
        #pragma unroll
        for (int v = 0; v < 4; v++) {
            bb1 = __ldg(&b1[tn * 4 + v]);
            #pragma unroll
            for (int u = 0; u < 4; u++) acc[u][v] = bb1;
        }
    }
    #pragma unroll 4
    for (int k = 0; k < 128; k++) {
        float4 a = *(const float4*)&bufA[k * A1S + tm * 4];
        float4 b = *(const float4*)&bufB[k * B1S + tn * 4];
        acc[0][0] = fmaf(a.x, b.x, acc[0][0]); acc[0][1] = fmaf(a.x, b.y, acc[0][1]);
        acc[0][2] = fmaf(a.x, b.z, acc[0][2]); acc[0][3] = fmaf(a.x, b.w, acc[0][3]);
        acc[1][0] = fmaf(a.y, b.x, acc[1][0]); acc[1][1] = fmaf(a.y, b.y, acc[1][1]);
        acc[1][2] = fmaf(a.y, b.z, acc[1][2]); acc[1][3] = fmaf(a.y, b.w, acc[1][3]);
        acc[2][0] = fmaf(a.z, b.x, acc[2][0]); acc[2][1] = fmaf(a.z, b.y, acc[2][1]);
        acc[2][2] = fmaf(a.z, b.z, acc[2][2]); acc[2][3] = fmaf(a.z, b.w, acc[2][3]);
        acc[3][0] = fmaf(a.w, b.x, acc[3][0]); acc[3][1] = fmaf(a.w, b.y, acc[3][1]);
        acc[3][2] = fmaf(a.w, b.z, acc[3][2]); acc[3][3] = fmaf(a.w, b.w, acc[3][3]);
    }
    __syncthreads();   // done with As1/Bs1 contents

    // relu -> As2[h][m] (in bufB); stage Bs2 (W2 k-major) into bufA
    #pragma unroll
    for (int v = 0; v < 4; v++)
        #pragma unroll
        for (int u = 0; u < 4; u++)
            bufB[(tn * 4 + v) * A2S + tm * 4 + u] = fmaxf(acc[u][v], 0.f);
    for (int idx = tid; idx < 2048; idx += 256) {
        int h = idx >> 5, t4 = idx & 31;
        float4 v = *(const float4*)&W2[(size_t)h * T_ + 4 * t4];
        *(float4*)&bufA[h * B2S + 4 * t4] = v;
    }
    __syncthreads();

    // phase 2 GEMM: acc2[4m][8t]
    float acc2[4][8];
    #pragma unroll
    for (int v = 0; v < 8; v++) {
        float bb2 = __ldg(&b2[tn * 8 + v]);
        #pragma unroll
        for (int u = 0; u < 4; u++) acc2[u][v] = bb2;
    }
    #pragma unroll 4
    for (int k = 0; k < 64; k++) {
        float4 a  = *(const float4*)&bufB[k * A2S + tm * 4];
        float4 c0 = *(const float4*)&bufA[k * B2S + tn * 8];
        float4 c1 = *(const float4*)&bufA[k * B2S + tn * 8 + 4];
        #pragma unroll
        for (int u = 0; u < 4; u++) {
            float av = (u == 0) ? a.x : (u == 1) ? a.y : (u == 2) ? a.z : a.w;
            acc2[u][0] = fmaf(av, c0.x, acc2[u][0]);
            acc2[u][1] = fmaf(av, c0.y, acc2[u][1]);
            acc2[u][2] = fmaf(av, c0.z, acc2[u][2]);
            acc2[u][3] = fmaf(av, c0.w, acc2[u][3]);
            acc2[u][4] = fmaf(av, c1.x, acc2[u][4]);
            acc2[u][5] = fmaf(av, c1.y, acc2[u][5]);
            acc2[u][6] = fmaf(av, c1.z, acc2[u][6]);
            acc2[u][7] = fmaf(av, c1.w, acc2[u][7]);
        }
    }

    // softmax over t: 16 threads (same tm, xor offsets 1,2,4,8 stay in group)
    #pragma unroll
    for (int u = 0; u < 4; u++) {
        float mx = acc2[u][0];
        #pragma unroll
        for (int v = 1; v < 8; v++) mx = fmaxf(mx, acc2[u][v]);
        #pragma unroll
        for (int o = 8; o; o >>= 1) mx = fmaxf(mx, __shfl_xor_sync(0xffffffffu, mx, o));
        float sum = 0.f;
        #pragma unroll
        for (int v = 0; v < 8; v++) { acc2[u][v] = expf(acc2[u][v] - mx); sum += acc2[u][v]; }
        #pragma unroll
        for (int o = 8; o; o >>= 1) sum += __shfl_xor_sync(0xffffffffu, sum, o);
        float inv = 1.0f / sum;
        #pragma unroll
        for (int v = 0; v < 8; v++)
            sout[(tn * 8 + v) * SOS + tm * 4 + u] = acc2[u][v] * inv;
    }
    __syncthreads();

    // coalesced transposed store: attn_out[t][b]
    for (int i = tid; i < 128 * 64; i += 256) {
        int t = i >> 6, m = i & 63;
        attn_out[(size_t)t * B_ + b0 + m] = sout[t * SOS + m];
    }
}

// ---------------- kernel 3: z via complement sparsity + softsign ------------
// z[n][b] = rowsum(x)[b] - sum_{j in zero-set(n)} x[b][idx] ; exactly 26 terms.
#define KZS_SMEM_BYTES ((129 * 132 + 128) * 4)
__global__ __launch_bounds__(128)
void kz_sparse_kernel(const float* __restrict__ xT, const int* __restrict__ cidx,
                      const float* __restrict__ thr, float* __restrict__ s_out) {
    extern __shared__ float sms[];
    float* xs = sms;                 // [129][132]
    float* rs = sms + 129 * 132;     // [128]
    int tid = threadIdx.x, w = tid >> 5, lane = tid & 31;
    int b0 = blockIdx.x * 128, n0 = blockIdx.y * 128;

    for (int it = tid; it < 128 * 32; it += 128) {
        int i = it >> 5, c = it & 31;
        float4 v = *(const float4*)&xT[(size_t)i * B_ + b0 + c * 4];
        *(float4*)&xs[i * 132 + c * 4] = v;
    }
    xs[128 * 132 + tid] = 0.f;
    __syncthreads();

    {
        float s0 = 0.f, s1 = 0.f, s2 = 0.f, s3 = 0.f;
        for (int i = 0; i < I_; i += 4) {
            s0 += xs[(i + 0) * 132 + tid];
            s1 += xs[(i + 1) * 132 + tid];
            s2 += xs[(i + 2) * 132 + tid];
            s3 += xs[(i + 3) * 132 + tid];
        }
        rs[tid] = (s0 + s1) + (s2 + s3);
    }
    __syncthreads();

    const u64x NEG2 = 0xbf800000bf800000ULL;
    const u64x ONE2 = 0x3f8000003f800000ULL;

    for (int q = 0; q < 32; q++) {
        int n = n0 + w * 32 + q;
        const int* ci = cidx + n * NZC;
        double2 r2 = *(const double2*)&rs[lane * 4];
        u64x aE01 = d2u(r2.x), aO01 = 0;
        u64x aE23 = d2u(r2.y), aO23 = 0;
        #pragma unroll
        for (int j = 0; j < NZC; j += 2) {
            int i0 = __ldg(ci + j);
            int i1 = __ldg(ci + j + 1);
            double2 x0 = *(const double2*)&xs[i0 * 132 + lane * 4];
            double2 x1 = *(const double2*)&xs[i1 * 132 + lane * 4];
            aE01 = fma2_(d2u(x0.x), NEG2, aE01);
            aE23 = fma2_(d2u(x0.y), NEG2, aE23);
            aO01 = fma2_(d2u(x1.x), NEG2, aO01);
            aO23 = fma2_(d2u(x1.y), NEG2, aO23);
        }
        u64x a01 = fma2_(aO01, ONE2, aE01);
        u64x a23 = fma2_(aO23, ONE2, aE23);

        float th = __ldg(&thr[n]);
        float z0, z1, z2, z3;
        upk2(z0, z1, a01); upk2(z2, z3, a23);
        z0 -= th; z1 -= th; z2 -= th; z3 -= th;
        float4 o;
        o.x = fmaf(0.5f, __fdividef(z0, 1.0f + fabsf(z0)), 0.5f);
        o.y = fmaf(0.5f, __fdividef(z1, 1.0f + fabsf(z1)), 0.5f);
        o.z = fmaf(0.5f, __fdividef(z2, 1.0f + fabsf(z2)), 0.5f);
        o.w = fmaf(0.5f, __fdividef(z3, 1.0f + fabsf(z3)), 0.5f);
        *(float4*)&s_out[(size_t)n * B_ + b0 + lane * 4] = o;
    }
}

// ---------------- kernel 4: leaf mix, shared slab + software pipeline -------
#define KMIX_SMEM_FLOATS (2 * L_ * LPROW)     // double-buffered slab, 24KB
__global__ __launch_bounds__(128, 3)
void kmix_kernel(const float* __restrict__ s_in, const float* __restrict__ attn,
                 const float* __restrict__ lp, float* __restrict__ part) {
    extern __shared__ float smm[];
    int tid = threadIdx.x;
    int bbase = blockIdx.x * 512;
    int ts = blockIdx.y;
    int t0 = ts * 2;

    const u64x ONE2 = 0x3f8000003f800000ULL;
    const u64x NEG2 = 0xbf800000bf800000ULL;

    u64x acc[C_][2];
    #pragma unroll
    for (int c = 0; c < C_; c++) { acc[c][0] = 0; acc[c][1] = 0; }

    {
        const float4* src = (const float4*)(lp + (size_t)t0 * (L_ * LPROW));
        float4* dst = (float4*)smm;
        #pragma unroll
        for (int k = 0; k < 6; k++) dst[tid + 128 * k] = src[tid + 128 * k];
    }
    __syncthreads();

    #pragma unroll
    for (int tt = 0; tt < 2; tt++) {
        int t = t0 + tt;
        if (tt == 0) {
            const float4* src = (const float4*)(lp + (size_t)(t0 + 1) * (L_ * LPROW));
            float4* dst = (float4*)(smm + L_ * LPROW);
            #pragma unroll
            for (int k = 0; k < 6; k++) dst[tid + 128 * k] = src[tid + 128 * k];
        }
        const float* slab = smm + tt * (L_ * LPROW);

        u64x sv0[D_], mv0[D_], sv1[D_], mv1[D_];
        const float* sp = s_in + (size_t)(t * D_) * B_ + bbase + tid;
        #pragma unroll
        for (int d = 0; d < D_; d++) {
            const float* q = sp + (size_t)d * B_;
            sv0[d] = pk2(q[0],   q[128]);
            sv1[d] = pk2(q[256], q[384]);
            mv0[d] = fma2_(sv0[d], NEG2, ONE2);
            mv1[d] = fma2_(sv1[d], NEG2, ONE2);
        }
        const float* ap = attn + (size_t)t * B_ + bbase + tid;
        u64x a0 = pk2(ap[0],   ap[128]);
        u64x a1 = pk2(ap[256], ap[384]);

        u64x pl0[8], pl1[8];
        pl0[0] = sv0[0]; pl0[1] = mv0[0];
        pl1[0] = sv1[0]; pl1[1] = mv1[0];
        pl0[2] = mul2_(pl0[0], mv0[1]); pl0[3] = mul2_(pl0[1], mv0[1]);
        pl1[2] = mul2_(pl1[0], mv1[1]); pl1[3] = mul2_(pl1[1], mv1[1]);
        pl0[0] = mul2_(pl0[0], sv0[1]); pl0[1] = mul2_(pl0[1], sv0[1]);
        pl1[0] = mul2_(pl1[0], sv1[1]); pl1[1] = mul2_(pl1[1], sv1[1]);
        pl0[4] = mul2_(pl0[0], mv0[2]); pl0[5] = mul2_(pl0[1], mv0[2]);
        pl0[6] = mul2_(pl0[2], mv0[2]); pl0[7] = mul2_(pl0[3], mv0[2]);
        pl1[4] = mul2_(pl1[0], mv1[2]); pl1[5] = mul2_(pl1[1], mv1[2]);
        pl1[6] = mul2_(pl1[2], mv1[2]); pl1[7] = mul2_(pl1[3], mv1[2]);
        pl0[0] = mul2_(pl0[0], sv0[2]); pl0[1] = mul2_(pl0[1], sv0[2]);
        pl0[2] = mul2_(pl0[2], sv0[2]); pl0[3] = mul2_(pl0[3], sv0[2]);
        pl1[0] = mul2_(pl1[0], sv1[2]); pl1[1] = mul2_(pl1[1], sv1[2]);
        pl1[2] = mul2_(pl1[2], sv1[2]); pl1[3] = mul2_(pl1[3], sv1[2]);

        u64x t00 = mul2_(a0, sv0[3]), t01 = mul2_(a0, mv0[3]);
        u64x t10 = mul2_(a1, sv1[3]), t11 = mul2_(a1, mv1[3]);
        u64x ph40[4], ph41[4], f0[4], f1[4];
        ph40[0] = mul2_(t00, sv0[4]); ph40[1] = mul2_(t01, sv0[4]);
        ph40[2] = mul2_(t00, mv0[4]); ph40[3] = mul2_(t01, mv0[4]);
        ph41[0] = mul2_(t10, sv1[4]); ph41[1] = mul2_(t11, sv1[4]);
        ph41[2] = mul2_(t10, mv1[4]); ph41[3] = mul2_(t11, mv1[4]);
        f0[0] = mul2_(sv0[5], sv0[6]); f0[1] = mul2_(mv0[5], sv0[6]);
        f0[2] = mul2_(sv0[5], mv0[6]); f0[3] = mul2_(mv0[5], mv0[6]);
        f1[0] = mul2_(sv1[5], sv1[6]); f1[1] = mul2_(mv1[5], sv1[6]);
        f1[2] = mul2_(sv1[5], mv1[6]); f1[3] = mul2_(mv1[5], mv1[6]);

        double2 buf[2][5];
        buf[0][0] = *(const double2*)(slab);
        buf[0][1] = *(const double2*)(slab + 4);
        buf[0][2] = *(const double2*)(slab + 8);
        buf[0][3] = *(const double2*)(slab + 12);
        buf[0][4] = *(const double2*)(slab + 16);
        #pragma unroll
        for (int m = 0; m < 16; m++) {
            u64x pm0 = mul2_(ph40[m & 3], f0[m >> 2]);
            u64x pm1 = mul2_(ph41[m & 3], f1[m >> 2]);
            #pragma unroll
            for (int j = 0; j < 8; j++) {
                int l = m * 8 + j;
                int p = l & 1, np = p ^ 1;
                const float* Ln = slab + ((l + 1) & 127) * LPROW;
                buf[np][0] = *(const double2*)(Ln);
                buf[np][1] = *(const double2*)(Ln + 4);
                buf[np][2] = *(const double2*)(Ln + 8);
                buf[np][3] = *(const double2*)(Ln + 12);
                buf[np][4] = *(const double2*)(Ln + 16);
                u64x q0 = mul2_(pl0[j], pm0);
                u64x q1 = mul2_(pl1[j], pm1);
                acc[0][0] = fma2_(q0, d2u(buf[p][0].x), acc[0][0]);
                acc[0][1] = fma2_(q1, d2u(buf[p][0].x), acc[0][1]);
                acc[1][0] = fma2_(q0, d2u(buf[p][0].y), acc[1][0]);
                acc[1][1] = fma2_(q1, d2u(buf[p][0].y), acc[1][1]);
                acc[2][0] = fma2_(q0, d2u(buf[p][1].x), acc[2][0]);
                acc[2][1] = fma2_(q1, d2u(buf[p][1].x), acc[2][1]);
                acc[3][0] = fma2_(q0, d2u(buf[p][1].y), acc[3][0]);
                acc[3][1] = fma2_(q1, d2u(buf[p][1].y), acc[3][1]);
                acc[4][0] = fma2_(q0, d2u(buf[p][2].x), acc[4][0]);
                acc[4][1] = fma2_(q1, d2u(buf[p][2].x), acc[4][1]);
                acc[5][0] = fma2_(q0, d2u(buf[p][2].y), acc[5][0]);
                acc[5][1] = fma2_(q1, d2u(buf[p][2].y), acc[5][1]);
                acc[6][0] = fma2_(q0, d2u(buf[p][3].x), acc[6][0]);
                acc[6][1] = fma2_(q1, d2u(buf[p][3].x), acc[6][1]);
                acc[7][0] = fma2_(q0, d2u(buf[p][3].y), acc[7][0]);
                acc[7][1] = fma2_(q1, d2u(buf[p][3].y), acc[7][1]);
                acc[8][0] = fma2_(q0, d2u(buf[p][4].x), acc[8][0]);
                acc[8][1] = fma2_(q1, d2u(buf[p][4].x), acc[8][1]);
                acc[9][0] = fma2_(q0, d2u(buf[p][4].y), acc[9][0]);
                acc[9][1] = fma2_(q1, d2u(buf[p][4].y), acc[9][1]);
            }
        }
        __syncthreads();
    }

    #pragma unroll
    for (int c = 0; c < C_; c++) {
        float v0, v1, v2, v3;
        upk2(v0, v1, acc[c][0]);
        upk2(v2, v3, acc[c][1]);
        float* o = part + ((size_t)ts * C_ + c) * B_ + bbase + tid;
        o[0]   = v0;
        o[128] = v1;
        o[256] = v2;
        o[384] = v3;
    }
}

// ---------------- kernel 5: sum the NSPLIT planar partials ----------------
__global__ __launch_bounds__(256)
void reduce_kernel(const float* __restrict__ part, float* __restrict__ out) {
    int idx = blockIdx.x * blockDim.x + threadIdx.x;    // c*B + b
    if (idx >= B_ * C_) return;
    int c = idx >> 13;           // / B_
    int b = idx & (B_ - 1);
    float s = 0.f;
    #pragma unroll
    for (int k = 0; k < NSPLIT; k++)
        s += part[((size_t)k * C_ + c) * B_ + b];
    out[(size_t)b * C_ + c] = s;
}

// ---------------- launcher ----------------
extern "C" void kernel_launch(void* const* d_in, const int* in_sizes, int n_in,
                              void* d_out, int out_size) {
    const float* x    = (const float*)d_in[0];
    const float* fm   = (const float*)d_in[1];
    const float* thr  = (const float*)d_in[2];
    const float* leaf = (const float*)d_in[3];
    const float* W1   = (const float*)d_in[4];
    const float* b1   = (const float*)d_in[5];
    const float* W2   = (const float*)d_in[6];
    const float* b2   = (const float*)d_in[7];
    float* out = (float*)d_out;

    float *gLP, *gAt, *gS, *gP, *gXT;
    int* gCI;
    cudaGetSymbolAddress((void**)&gLP, g_LP);
    cudaGetSymbolAddress((void**)&gAt, g_attn);
    cudaGetSymbolAddress((void**)&gS,  g_s);
    cudaGetSymbolAddress((void**)&gP,  g_part);
    cudaGetSymbolAddress((void**)&gXT, g_xT);
    cudaGetSymbolAddress((void**)&gCI, g_cidx);

    cudaFuncSetAttribute(attn_kernel, cudaFuncAttributeMaxDynamicSharedMemorySize,
                         ATTN_SMEM_FLOATS * 4);
    cudaFuncSetAttribute(kz_sparse_kernel, cudaFuncAttributeMaxDynamicSharedMemorySize,
                         KZS_SMEM_BYTES);
    cudaFuncSetAttribute(kmix_kernel, cudaFuncAttributeMaxDynamicSharedMemorySize,
                         KMIX_SMEM_FLOATS * 4);
    (void)in_sizes; (void)n_in; (void)out_size;

    prep_leaf_kernel<<<(T_ * L_ + 255) / 256, 256>>>(leaf, gLP);
    prep_cidx_kernel<<<(TD_ + 127) / 128, 128>>>(fm, gCI);
    xpose_kernel<<<dim3(B_ / 32, I_ / 32), 256>>>(x, gXT);
    attn_kernel<<<B_ / 64, 256, ATTN_SMEM_FLOATS * 4>>>(x, W1, b1, W2, b2, gAt);
    kz_sparse_kernel<<<dim3(B_ / 128, TD_ / 128), 128, KZS_SMEM_BYTES>>>(gXT, gCI, thr, gS);
    kmix_kernel<<<dim3(B_ / 512, NSPLIT), 128, KMIX_SMEM_FLOATS * 4>>>(gS, gAt, gLP, gP);
    reduce_kernel<<<(B_ * C_ + 255) / 256, 256>>>(gP, out);
}